// round 1
// baseline (speedup 1.0000x reference)
#include <cuda_runtime.h>

#define NB    8
#define SEQ   1024
#define CH    576
#define NHEAD 6
#define HDIM  96
#define MR    (NB*SEQ)          // 8192 rows for projections

// Scratch for Q/K/V projection outputs, [b][k][c] row-major == [b][h][d][t] scrambled view.
__device__ float g_Q[NB*SEQ*CH];
__device__ float g_K[NB*SEQ*CH];
__device__ float g_V[NB*SEQ*CH];

// ---------------------------------------------------------------------------
// Projection: Y = X @ W^T + bias.  X:[8192,576], W:[576,576] row-major.
// grid (9 n-tiles, 128 m-tiles, 3 {q,k,v}), 256 threads, 64x64 tile, BK=16.
// ---------------------------------------------------------------------------
__global__ __launch_bounds__(256) void proj_kernel(
    const float* __restrict__ x1, const float* __restrict__ x2,
    const float* __restrict__ Wq, const float* __restrict__ bq,
    const float* __restrict__ Wk, const float* __restrict__ bk,
    const float* __restrict__ Wv, const float* __restrict__ bv)
{
    const int which = blockIdx.z;
    const float* X    = (which == 0) ? x1 : x2;
    const float* W    = (which == 0) ? Wq : (which == 1) ? Wk : Wv;
    const float* bias = (which == 0) ? bq : (which == 1) ? bk : bv;
    float*       Y    = (which == 0) ? g_Q : (which == 1) ? g_K : g_V;

    __shared__ float Xs[16][68];   // Xs[c][m], pad 68 to break write conflicts
    __shared__ float Ws[16][68];   // Ws[c][n]

    const int tid = threadIdx.x;
    const int tx  = tid & 15;      // 0..15
    const int ty  = tid >> 4;      // 0..15
    const int n0  = blockIdx.x * 64;
    const int m0  = blockIdx.y * 64;

    float acc[4][4];
#pragma unroll
    for (int i = 0; i < 4; i++)
#pragma unroll
        for (int j = 0; j < 4; j++) acc[i][j] = 0.f;

    for (int c0 = 0; c0 < CH; c0 += 16) {
        // load tiles: lanes read 16 consecutive cols (coalesced 64B segments)
#pragma unroll
        for (int r = 0; r < 4; r++) {
            int m = ty + r * 16;                    // 0..63
            Xs[tx][m] = X[(size_t)(m0 + m) * CH + c0 + tx];
            Ws[tx][m] = W[(size_t)(n0 + m) * CH + c0 + tx];
        }
        __syncthreads();
#pragma unroll
        for (int kk = 0; kk < 16; kk++) {
            float4 a = *(const float4*)&Xs[kk][ty * 4];
            float4 b = *(const float4*)&Ws[kk][tx * 4];
            float av[4] = {a.x, a.y, a.z, a.w};
            float bv2[4] = {b.x, b.y, b.z, b.w};
#pragma unroll
            for (int i = 0; i < 4; i++)
#pragma unroll
                for (int j = 0; j < 4; j++)
                    acc[i][j] = fmaf(av[i], bv2[j], acc[i][j]);
        }
        __syncthreads();
    }

#pragma unroll
    for (int i = 0; i < 4; i++) {
        int m = m0 + ty * 4 + i;
        float4 o;
        o.x = acc[i][0] + bias[n0 + tx * 4 + 0];
        o.y = acc[i][1] + bias[n0 + tx * 4 + 1];
        o.z = acc[i][2] + bias[n0 + tx * 4 + 2];
        o.w = acc[i][3] + bias[n0 + tx * 4 + 3];
        *(float4*)&Y[(size_t)m * CH + n0 + tx * 4] = o;
    }
}

// ---------------------------------------------------------------------------
// Fused flash-style attention over the scrambled view.
// Per (b,h): Q,K,V are [96][1024] with row stride 1024 (t contiguous) at
// base = b*SEQ*CH + h*HDIM*SEQ.  S = Q^T K (64q x 64k tiles), online softmax,
// O[q][d] accumulated in registers, out written at the same flat offsets.
// grid (16 q-tiles, 6 heads, 8 batch), 256 threads.
// ---------------------------------------------------------------------------
#define TQ 64
#define TK 64
#define PSTRIDE 68   // padded row stride for Ps

// smem layout (floats):
//  Qs [96][64]   @ 0       (6144)
//  Ks [96][64]   @ 6144    (6144)
//  Vs [96][64]   @ 12288   (6144)
//  Ps [64][68]   @ 18432   (4352)
//  m_s[64]       @ 22784
//  l_s[64]       @ 22848
//  a_s[64]       @ 22912
//  total 22976 floats = 91904 bytes
#define ATTN_SMEM_FLOATS 22976
#define ATTN_SMEM_BYTES  (ATTN_SMEM_FLOATS * 4)

__global__ __launch_bounds__(256) void attn_kernel(float* __restrict__ out)
{
    extern __shared__ float sm[];
    float* Qs  = sm;
    float* Ks  = sm + 6144;
    float* Vs  = sm + 12288;
    float* Ps  = sm + 18432;
    float* m_s = sm + 22784;
    float* l_s = sm + 22848;
    float* a_s = sm + 22912;

    const int tid = threadIdx.x;
    const int q0  = blockIdx.x * TQ;
    const int h   = blockIdx.y;
    const int b   = blockIdx.z;
    const size_t base = (size_t)b * (SEQ * CH) + (size_t)h * (HDIM * SEQ);

    // load Q tile: Qs[d][q]
    for (int idx = tid; idx < HDIM * TQ; idx += 256) {
        int d = idx >> 6, q = idx & 63;
        Qs[d * TQ + q] = g_Q[base + (size_t)d * SEQ + q0 + q];
    }
    if (tid < TQ) { m_s[tid] = -1e30f; l_s[tid] = 0.f; }

    // persistent output accumulators: unit u -> (qi = (tid+u*256)&63, dg = (tid+u*256)>>6)
    float O[6][4];
#pragma unroll
    for (int u = 0; u < 6; u++)
#pragma unroll
        for (int j = 0; j < 4; j++) O[u][j] = 0.f;

    const int tx = tid & 15;   // key group in S phase
    const int ty = tid >> 4;   // query group in S phase

    for (int t0 = 0; t0 < SEQ; t0 += TK) {
        __syncthreads();   // prev PV done (Vs/Ps free); Q load + stats init visible
        for (int idx = tid; idx < HDIM * TK; idx += 256) {
            int d = idx >> 6, k = idx & 63;
            Ks[d * TK + k] = g_K[base + (size_t)d * SEQ + t0 + k];
            Vs[d * TK + k] = g_V[base + (size_t)d * SEQ + t0 + k];
        }
        __syncthreads();

        // ---- S = Q^T K over head dim (96) ----
        float S[4][4];
#pragma unroll
        for (int i = 0; i < 4; i++)
#pragma unroll
            for (int j = 0; j < 4; j++) S[i][j] = 0.f;

#pragma unroll 8
        for (int d = 0; d < HDIM; d++) {
            float4 qa = *(const float4*)&Qs[d * TQ + ty * 4];
            float4 kb = *(const float4*)&Ks[d * TK + tx * 4];
            float qv[4] = {qa.x, qa.y, qa.z, qa.w};
            float kv[4] = {kb.x, kb.y, kb.z, kb.w};
#pragma unroll
            for (int i = 0; i < 4; i++)
#pragma unroll
                for (int j = 0; j < 4; j++)
                    S[i][j] = fmaf(qv[i], kv[j], S[i][j]);
        }

        // ---- online softmax per query row (row owned by 16 lanes of one ty) ----
#pragma unroll
        for (int i = 0; i < 4; i++) {
            int q = ty * 4 + i;
            float mloc = fmaxf(fmaxf(S[i][0], S[i][1]), fmaxf(S[i][2], S[i][3]));
#pragma unroll
            for (int off = 8; off >= 1; off >>= 1)
                mloc = fmaxf(mloc, __shfl_xor_sync(0xFFFFFFFFu, mloc, off));
            float mold = m_s[q];
            float mnew = fmaxf(mold, mloc);
            float p[4], rs = 0.f;
#pragma unroll
            for (int j = 0; j < 4; j++) { p[j] = __expf(S[i][j] - mnew); rs += p[j]; }
#pragma unroll
            for (int off = 8; off >= 1; off >>= 1)
                rs += __shfl_xor_sync(0xFFFFFFFFu, rs, off);
            if (tx == 0) {
                float al = __expf(mold - mnew);
                a_s[q] = al;
                l_s[q] = l_s[q] * al + rs;
                m_s[q] = mnew;
            }
            *(float4*)&Ps[q * PSTRIDE + tx * 4] = make_float4(p[0], p[1], p[2], p[3]);
        }
        __syncthreads();

        // ---- O[q][d] = O*alpha + P @ V^T ----
#pragma unroll
        for (int u = 0; u < 6; u++) {
            int unit = tid + u * 256;
            int qi = unit & 63;
            int dg = unit >> 6;          // 0..23, 4 dims each
            float al = a_s[qi];
#pragma unroll
            for (int j = 0; j < 4; j++) O[u][j] *= al;
#pragma unroll 4
            for (int k4 = 0; k4 < 16; k4++) {
                float4 p = *(const float4*)&Ps[qi * PSTRIDE + k4 * 4];
#pragma unroll
                for (int j = 0; j < 4; j++) {
                    float4 v = *(const float4*)&Vs[(dg * 4 + j) * TK + k4 * 4];
                    O[u][j] = fmaf(p.x, v.x, O[u][j]);
                    O[u][j] = fmaf(p.y, v.y, O[u][j]);
                    O[u][j] = fmaf(p.z, v.z, O[u][j]);
                    O[u][j] = fmaf(p.w, v.w, O[u][j]);
                }
            }
        }
    }

    // ---- finalize: divide by l, write at scrambled-view offsets (coalesced in q) ----
#pragma unroll
    for (int u = 0; u < 6; u++) {
        int unit = tid + u * 256;
        int qi = unit & 63;
        int dg = unit >> 6;
        float inv = 1.f / l_s[qi];
#pragma unroll
        for (int j = 0; j < 4; j++)
            out[base + (size_t)(dg * 4 + j) * SEQ + q0 + qi] = O[u][j] * inv;
    }
}

// ---------------------------------------------------------------------------
extern "C" void kernel_launch(void* const* d_in, const int* in_sizes, int n_in,
                              void* d_out, int out_size)
{
    (void)in_sizes; (void)n_in; (void)out_size;
    const float* x1 = (const float*)d_in[0];
    const float* x2 = (const float*)d_in[1];
    const float* Wq = (const float*)d_in[2];
    const float* bq = (const float*)d_in[3];
    const float* Wk = (const float*)d_in[4];
    const float* bk = (const float*)d_in[5];
    const float* Wv = (const float*)d_in[6];
    const float* bv = (const float*)d_in[7];
    float* out = (float*)d_out;

    cudaFuncSetAttribute(attn_kernel, cudaFuncAttributeMaxDynamicSharedMemorySize,
                         ATTN_SMEM_BYTES);

    proj_kernel<<<dim3(9, 128, 3), 256>>>(x1, x2, Wq, bq, Wk, bk, Wv, bv);
    attn_kernel<<<dim3(16, NHEAD, NB), 256, ATTN_SMEM_BYTES>>>(out);
}

// round 3
// speedup vs baseline: 1.2243x; 1.2243x over previous
#include <cuda_runtime.h>
#include <cstdint>

#define NB    8
#define SEQ   1024
#define CH    576
#define NHEAD 6
#define HDIM  96

__device__ float g_Q[NB*SEQ*CH];
__device__ float g_K[NB*SEQ*CH];
__device__ float g_V[NB*SEQ*CH];

// round fp32 -> tf32 (RN), result is an fp32 bit-pattern
__device__ __forceinline__ uint32_t f2tf(float x) {
    uint32_t u;
    asm("cvt.rna.tf32.f32 %0, %1;" : "=r"(u) : "f"(x));
    return u;
}

__device__ __forceinline__ void mma_tf32(float& d0, float& d1, float& d2, float& d3,
                                         uint32_t a0, uint32_t a1, uint32_t a2, uint32_t a3,
                                         uint32_t b0, uint32_t b1) {
    asm volatile(
        "mma.sync.aligned.m16n8k8.row.col.f32.tf32.tf32.f32 "
        "{%0,%1,%2,%3},{%4,%5,%6,%7},{%8,%9},{%0,%1,%2,%3};"
        : "+f"(d0), "+f"(d1), "+f"(d2), "+f"(d3)
        : "r"(a0), "r"(a1), "r"(a2), "r"(a3), "r"(b0), "r"(b1));
}

// ---------------------------------------------------------------------------
// Projection: Y = X @ W^T + bias, 3x-tf32 split MMA (near-fp32 accuracy).
// CTA: 256 thr = 8 warps (4m x 2n), tile M=128 N=64, kc=32.
// grid (9 n-tiles, 64 m-tiles, 3 = {Q,K,V}); scratch outputs resolved in
// DEVICE code from blockIdx.z (never pass __device__ globals from host!).
// ---------------------------------------------------------------------------
#define PROJ_SMEM_BYTES ((2*128*36 + 2*64*36) * 4)

__global__ __launch_bounds__(256) void proj_mma(
    const float* __restrict__ x1, const float* __restrict__ x2,
    const float* __restrict__ Wq, const float* __restrict__ bq,
    const float* __restrict__ Wk, const float* __restrict__ bk,
    const float* __restrict__ Wv, const float* __restrict__ bv)
{
    const int which = blockIdx.z;
    const float* X    = (which == 0) ? x1 : x2;
    const float* W    = (which == 0) ? Wq : (which == 1) ? Wk : Wv;
    const float* bias = (which == 0) ? bq : (which == 1) ? bk : bv;
    float*       Y    = (which == 0) ? g_Q : (which == 1) ? g_K : g_V;

    extern __shared__ float sp[];
    float* Xhi = sp;                         // [128][36]
    float* Whi = sp + 128*36;                // [64][36]
    float* Xlo = sp + 128*36 + 64*36;        // [128][36]
    float* Wlo = sp + 2*128*36 + 64*36;      // [64][36]

    const int tid  = threadIdx.x;
    const int lane = tid & 31;
    const int w    = tid >> 5;
    const int wm   = w & 3, wn = w >> 2;
    const int r    = lane >> 2, c = lane & 3;
    const int n0   = blockIdx.x * 64;
    const int m0   = blockIdx.y * 128;

    float acc[2][4][4];
#pragma unroll
    for (int mi = 0; mi < 2; mi++)
#pragma unroll
        for (int f = 0; f < 4; f++)
#pragma unroll
            for (int j = 0; j < 4; j++) acc[mi][f][j] = 0.f;

    const int lrow = tid >> 3;        // 0..31
    const int lcol = (tid & 7) * 4;   // 0..28

    for (int c0 = 0; c0 < CH; c0 += 32) {
        __syncthreads();
#pragma unroll
        for (int p = 0; p < 4; p++) {
            int m = lrow + p * 32;
            float4 xv = *(const float4*)&X[(size_t)(m0 + m) * CH + c0 + lcol];
            float xs[4] = {xv.x, xv.y, xv.z, xv.w};
#pragma unroll
            for (int j = 0; j < 4; j++) {
                uint32_t hb = f2tf(xs[j]);
                Xhi[m * 36 + lcol + j] = __uint_as_float(hb);
                Xlo[m * 36 + lcol + j] =
                    __uint_as_float(f2tf(xs[j] - __uint_as_float(hb)));
            }
        }
#pragma unroll
        for (int p = 0; p < 2; p++) {
            int n = lrow + p * 32;
            float4 wv = *(const float4*)&W[(size_t)(n0 + n) * CH + c0 + lcol];
            float ws[4] = {wv.x, wv.y, wv.z, wv.w};
#pragma unroll
            for (int j = 0; j < 4; j++) {
                uint32_t hb = f2tf(ws[j]);
                Whi[n * 36 + lcol + j] = __uint_as_float(hb);
                Wlo[n * 36 + lcol + j] =
                    __uint_as_float(f2tf(ws[j] - __uint_as_float(hb)));
            }
        }
        __syncthreads();

#pragma unroll
        for (int ks = 0; ks < 4; ks++) {
            const int k = ks * 8 + c;
            uint32_t ahi[2][4], alo[2][4], bhi[4][2], blo[4][2];
#pragma unroll
            for (int mi = 0; mi < 2; mi++) {
                int mm = wm * 32 + mi * 16;
                ahi[mi][0] = __float_as_uint(Xhi[(mm + r) * 36 + k]);
                ahi[mi][1] = __float_as_uint(Xhi[(mm + r + 8) * 36 + k]);
                ahi[mi][2] = __float_as_uint(Xhi[(mm + r) * 36 + k + 4]);
                ahi[mi][3] = __float_as_uint(Xhi[(mm + r + 8) * 36 + k + 4]);
                alo[mi][0] = __float_as_uint(Xlo[(mm + r) * 36 + k]);
                alo[mi][1] = __float_as_uint(Xlo[(mm + r + 8) * 36 + k]);
                alo[mi][2] = __float_as_uint(Xlo[(mm + r) * 36 + k + 4]);
                alo[mi][3] = __float_as_uint(Xlo[(mm + r + 8) * 36 + k + 4]);
            }
#pragma unroll
            for (int f = 0; f < 4; f++) {
                int nn = wn * 32 + f * 8 + r;
                bhi[f][0] = __float_as_uint(Whi[nn * 36 + k]);
                bhi[f][1] = __float_as_uint(Whi[nn * 36 + k + 4]);
                blo[f][0] = __float_as_uint(Wlo[nn * 36 + k]);
                blo[f][1] = __float_as_uint(Wlo[nn * 36 + k + 4]);
            }
#pragma unroll
            for (int mi = 0; mi < 2; mi++)
#pragma unroll
                for (int f = 0; f < 4; f++) {
                    mma_tf32(acc[mi][f][0], acc[mi][f][1], acc[mi][f][2], acc[mi][f][3],
                             ahi[mi][0], ahi[mi][1], ahi[mi][2], ahi[mi][3],
                             bhi[f][0], bhi[f][1]);
                    mma_tf32(acc[mi][f][0], acc[mi][f][1], acc[mi][f][2], acc[mi][f][3],
                             ahi[mi][0], ahi[mi][1], ahi[mi][2], ahi[mi][3],
                             blo[f][0], blo[f][1]);
                    mma_tf32(acc[mi][f][0], acc[mi][f][1], acc[mi][f][2], acc[mi][f][3],
                             alo[mi][0], alo[mi][1], alo[mi][2], alo[mi][3],
                             bhi[f][0], bhi[f][1]);
                }
        }
    }

#pragma unroll
    for (int mi = 0; mi < 2; mi++)
#pragma unroll
        for (int f = 0; f < 4; f++) {
            int n = n0 + wn * 32 + f * 8 + 2 * c;
            float b0 = bias[n], b1 = bias[n + 1];
            int m = m0 + wm * 32 + mi * 16 + r;
            float2 o0 = make_float2(acc[mi][f][0] + b0, acc[mi][f][1] + b1);
            float2 o1 = make_float2(acc[mi][f][2] + b0, acc[mi][f][3] + b1);
            *(float2*)&Y[(size_t)m * CH + n] = o0;
            *(float2*)&Y[(size_t)(m + 8) * CH + n] = o1;
        }
}

// ---------------------------------------------------------------------------
// Fused attention, tf32 MMA.  S = Q^T K: 3x-tf32; PV: P split hi/lo (2x), V 1x.
// CTA: 128 thr = 4 warps, q-tile 64 (16 q/warp), TK=64.
// smem: Khi[96][72] Klo[96][72] Vs[96][68] union{Qst[96][72] | Pshi+Pslo}
// ---------------------------------------------------------------------------
#define SM_KHI 0
#define SM_KLO (96*72)
#define SM_VS  (2*96*72)
#define SM_UN  (2*96*72 + 96*68)             // union base
#define SM_PLO (SM_UN + 4*16*68)             // Ps-lo base
#define ATTN_SMEM_FLOATS (SM_UN + 2*4*16*68) // 29056
#define ATTN_SMEM_BYTES  (ATTN_SMEM_FLOATS*4)

__global__ __launch_bounds__(128) void attn_mma(float* __restrict__ out)
{
    extern __shared__ float sm[];
    float* Khi  = sm + SM_KHI;
    float* Klo  = sm + SM_KLO;
    float* Vs   = sm + SM_VS;
    float* Qst  = sm + SM_UN;
    float* Pshi = sm + SM_UN  + (threadIdx.x >> 5) * (16 * 68);
    float* Pslo = sm + SM_PLO + (threadIdx.x >> 5) * (16 * 68);

    const int tid  = threadIdx.x;
    const int lane = tid & 31;
    const int w    = tid >> 5;
    const int r    = lane >> 2;
    const int c    = lane & 3;
    const int q0   = blockIdx.x * 64;
    const size_t base = (size_t)blockIdx.z * (SEQ * CH) + (size_t)blockIdx.y * (HDIM * SEQ);

    for (int idx = tid; idx < HDIM * 64; idx += 128) {
        int d = idx >> 6, q = idx & 63;
        Qst[d * 72 + q] = g_Q[base + (size_t)d * SEQ + q0 + q];
    }
    __syncthreads();

    uint32_t qhi[12][4], qlo[12][4];
    const int qm = w * 16 + r;
#pragma unroll
    for (int ks = 0; ks < 12; ks++) {
        float v0 = Qst[(8 * ks + c) * 72 + qm];
        float v1 = Qst[(8 * ks + c) * 72 + qm + 8];
        float v2 = Qst[(8 * ks + c + 4) * 72 + qm];
        float v3 = Qst[(8 * ks + c + 4) * 72 + qm + 8];
        qhi[ks][0] = f2tf(v0); qlo[ks][0] = f2tf(v0 - __uint_as_float(qhi[ks][0]));
        qhi[ks][1] = f2tf(v1); qlo[ks][1] = f2tf(v1 - __uint_as_float(qhi[ks][1]));
        qhi[ks][2] = f2tf(v2); qlo[ks][2] = f2tf(v2 - __uint_as_float(qhi[ks][2]));
        qhi[ks][3] = f2tf(v3); qlo[ks][3] = f2tf(v3 - __uint_as_float(qhi[ks][3]));
    }

    float O[12][4];
#pragma unroll
    for (int f = 0; f < 12; f++)
#pragma unroll
        for (int j = 0; j < 4; j++) O[f][j] = 0.f;
    float mrow[2] = {-1e30f, -1e30f};
    float lrow[2] = {0.f, 0.f};

    for (int t0 = 0; t0 < SEQ; t0 += 64) {
        __syncthreads();
        for (int idx = tid; idx < HDIM * 64; idx += 128) {
            int d = idx >> 6, k = idx & 63;
            float kv = g_K[base + (size_t)d * SEQ + t0 + k];
            uint32_t kh = f2tf(kv);
            Khi[d * 72 + k] = __uint_as_float(kh);
            Klo[d * 72 + k] = __uint_as_float(f2tf(kv - __uint_as_float(kh)));
            Vs[d * 68 + k]  = __uint_as_float(f2tf(g_V[base + (size_t)d * SEQ + t0 + k]));
        }
        __syncthreads();

        // ---- S = Q^T K (3x tf32) ----
        float S[8][4];
#pragma unroll
        for (int f = 0; f < 8; f++)
#pragma unroll
            for (int j = 0; j < 4; j++) S[f][j] = 0.f;

#pragma unroll
        for (int ks = 0; ks < 12; ks++) {
            const int kb = (8 * ks + c) * 72 + r;
#pragma unroll
            for (int f = 0; f < 8; f++) {
                uint32_t bh0 = __float_as_uint(Khi[kb + f * 8]);
                uint32_t bh1 = __float_as_uint(Khi[kb + f * 8 + 4 * 72]);
                uint32_t bl0 = __float_as_uint(Klo[kb + f * 8]);
                uint32_t bl1 = __float_as_uint(Klo[kb + f * 8 + 4 * 72]);
                mma_tf32(S[f][0], S[f][1], S[f][2], S[f][3],
                         qhi[ks][0], qhi[ks][1], qhi[ks][2], qhi[ks][3], bh0, bh1);
                mma_tf32(S[f][0], S[f][1], S[f][2], S[f][3],
                         qhi[ks][0], qhi[ks][1], qhi[ks][2], qhi[ks][3], bl0, bl1);
                mma_tf32(S[f][0], S[f][1], S[f][2], S[f][3],
                         qlo[ks][0], qlo[ks][1], qlo[ks][2], qlo[ks][3], bh0, bh1);
            }
        }

        // ---- online softmax (rows r, r+8 of this warp's 16-q block) ----
#pragma unroll
        for (int half = 0; half < 2; half++) {
            float mx = -1e30f;
#pragma unroll
            for (int f = 0; f < 8; f++)
                mx = fmaxf(mx, fmaxf(S[f][2 * half], S[f][2 * half + 1]));
            mx = fmaxf(mx, __shfl_xor_sync(0xFFFFFFFFu, mx, 1));
            mx = fmaxf(mx, __shfl_xor_sync(0xFFFFFFFFu, mx, 2));
            float mnew = fmaxf(mrow[half], mx);
            float al = __expf(mrow[half] - mnew);
            float rs = 0.f;
#pragma unroll
            for (int f = 0; f < 8; f++) {
                float p0 = __expf(S[f][2 * half] - mnew);
                float p1 = __expf(S[f][2 * half + 1] - mnew);
                rs += p0 + p1;
                uint32_t h0 = f2tf(p0), h1 = f2tf(p1);
                float l0 = p0 - __uint_as_float(h0);
                float l1 = p1 - __uint_as_float(h1);
                *(float2*)&Pshi[(r + 8 * half) * 68 + f * 8 + 2 * c] =
                    make_float2(__uint_as_float(h0), __uint_as_float(h1));
                *(float2*)&Pslo[(r + 8 * half) * 68 + f * 8 + 2 * c] =
                    make_float2(__uint_as_float(f2tf(l0)), __uint_as_float(f2tf(l1)));
            }
            rs += __shfl_xor_sync(0xFFFFFFFFu, rs, 1);
            rs += __shfl_xor_sync(0xFFFFFFFFu, rs, 2);
            lrow[half] = lrow[half] * al + rs;
            mrow[half] = mnew;
#pragma unroll
            for (int f = 0; f < 12; f++) {
                O[f][2 * half]     *= al;
                O[f][2 * half + 1] *= al;
            }
        }
        __syncwarp();

        // ---- O += (Phi + Plo) @ V^T ----
#pragma unroll
        for (int ks = 0; ks < 8; ks++) {
            uint32_t a0 = __float_as_uint(Pshi[r * 68 + ks * 8 + c]);
            uint32_t a1 = __float_as_uint(Pshi[(r + 8) * 68 + ks * 8 + c]);
            uint32_t a2 = __float_as_uint(Pshi[r * 68 + ks * 8 + c + 4]);
            uint32_t a3 = __float_as_uint(Pshi[(r + 8) * 68 + ks * 8 + c + 4]);
            uint32_t e0 = __float_as_uint(Pslo[r * 68 + ks * 8 + c]);
            uint32_t e1 = __float_as_uint(Pslo[(r + 8) * 68 + ks * 8 + c]);
            uint32_t e2 = __float_as_uint(Pslo[r * 68 + ks * 8 + c + 4]);
            uint32_t e3 = __float_as_uint(Pslo[(r + 8) * 68 + ks * 8 + c + 4]);
#pragma unroll
            for (int f = 0; f < 12; f++) {
                uint32_t b0 = __float_as_uint(Vs[(f * 8 + r) * 68 + ks * 8 + c]);
                uint32_t b1 = __float_as_uint(Vs[(f * 8 + r) * 68 + ks * 8 + c + 4]);
                mma_tf32(O[f][0], O[f][1], O[f][2], O[f][3], a0, a1, a2, a3, b0, b1);
                mma_tf32(O[f][0], O[f][1], O[f][2], O[f][3], e0, e1, e2, e3, b0, b1);
            }
        }
        __syncwarp();
    }

    float inv0 = 1.f / lrow[0];
    float inv1 = 1.f / lrow[1];
#pragma unroll
    for (int f = 0; f < 12; f++) {
        int d0 = f * 8 + 2 * c;
        int qa = q0 + w * 16 + r;
        out[base + (size_t)d0 * SEQ + qa]           = O[f][0] * inv0;
        out[base + (size_t)(d0 + 1) * SEQ + qa]     = O[f][1] * inv0;
        out[base + (size_t)d0 * SEQ + qa + 8]       = O[f][2] * inv1;
        out[base + (size_t)(d0 + 1) * SEQ + qa + 8] = O[f][3] * inv1;
    }
}

// ---------------------------------------------------------------------------
extern "C" void kernel_launch(void* const* d_in, const int* in_sizes, int n_in,
                              void* d_out, int out_size)
{
    (void)in_sizes; (void)n_in; (void)out_size;
    const float* x1 = (const float*)d_in[0];
    const float* x2 = (const float*)d_in[1];
    const float* Wq = (const float*)d_in[2];
    const float* bq = (const float*)d_in[3];
    const float* Wk = (const float*)d_in[4];
    const float* bk = (const float*)d_in[5];
    const float* Wv = (const float*)d_in[6];
    const float* bv = (const float*)d_in[7];
    float* out = (float*)d_out;

    cudaFuncSetAttribute(proj_mma, cudaFuncAttributeMaxDynamicSharedMemorySize,
                         PROJ_SMEM_BYTES);
    cudaFuncSetAttribute(attn_mma, cudaFuncAttributeMaxDynamicSharedMemorySize,
                         ATTN_SMEM_BYTES);

    proj_mma<<<dim3(9, 64, 3), 256, PROJ_SMEM_BYTES>>>(
        x1, x2, Wq, bq, Wk, bk, Wv, bv);
    attn_mma<<<dim3(16, NHEAD, NB), 128, ATTN_SMEM_BYTES>>>(out);
}

// round 4
// speedup vs baseline: 1.8634x; 1.5220x over previous
#include <cuda_runtime.h>
#include <cstdint>

#define NB    8
#define SEQ   1024
#define CH    576
#define NHEAD 6
#define HDIM  96

__device__ float g_Q[NB*SEQ*CH];
__device__ float g_K[NB*SEQ*CH];
__device__ float g_V[NB*SEQ*CH];

__device__ __forceinline__ uint32_t f2tf(float x) {
    uint32_t u;
    asm("cvt.rna.tf32.f32 %0, %1;" : "=r"(u) : "f"(x));
    return u;
}

__device__ __forceinline__ void mma_tf32(float& d0, float& d1, float& d2, float& d3,
                                         uint32_t a0, uint32_t a1, uint32_t a2, uint32_t a3,
                                         uint32_t b0, uint32_t b1) {
    asm volatile(
        "mma.sync.aligned.m16n8k8.row.col.f32.tf32.tf32.f32 "
        "{%0,%1,%2,%3},{%4,%5,%6,%7},{%8,%9},{%0,%1,%2,%3};"
        : "+f"(d0), "+f"(d1), "+f"(d2), "+f"(d3)
        : "r"(a0), "r"(a1), "r"(a2), "r"(a3), "r"(b0), "r"(b1));
}

// ---------------------------------------------------------------------------
// Projection: Y = X @ W^T + bias, 3x-tf32 split MMA. (unchanged from R3)
// ---------------------------------------------------------------------------
#define PROJ_SMEM_BYTES ((2*128*36 + 2*64*36) * 4)

__global__ __launch_bounds__(256) void proj_mma(
    const float* __restrict__ x1, const float* __restrict__ x2,
    const float* __restrict__ Wq, const float* __restrict__ bq,
    const float* __restrict__ Wk, const float* __restrict__ bk,
    const float* __restrict__ Wv, const float* __restrict__ bv)
{
    const int which = blockIdx.z;
    const float* X    = (which == 0) ? x1 : x2;
    const float* W    = (which == 0) ? Wq : (which == 1) ? Wk : Wv;
    const float* bias = (which == 0) ? bq : (which == 1) ? bk : bv;
    float*       Y    = (which == 0) ? g_Q : (which == 1) ? g_K : g_V;

    extern __shared__ float sp[];
    float* Xhi = sp;
    float* Whi = sp + 128*36;
    float* Xlo = sp + 128*36 + 64*36;
    float* Wlo = sp + 2*128*36 + 64*36;

    const int tid  = threadIdx.x;
    const int lane = tid & 31;
    const int w    = tid >> 5;
    const int wm   = w & 3, wn = w >> 2;
    const int r    = lane >> 2, c = lane & 3;
    const int n0   = blockIdx.x * 64;
    const int m0   = blockIdx.y * 128;

    float acc[2][4][4];
#pragma unroll
    for (int mi = 0; mi < 2; mi++)
#pragma unroll
        for (int f = 0; f < 4; f++)
#pragma unroll
            for (int j = 0; j < 4; j++) acc[mi][f][j] = 0.f;

    const int lrow = tid >> 3;
    const int lcol = (tid & 7) * 4;

    for (int c0 = 0; c0 < CH; c0 += 32) {
        __syncthreads();
#pragma unroll
        for (int p = 0; p < 4; p++) {
            int m = lrow + p * 32;
            float4 xv = *(const float4*)&X[(size_t)(m0 + m) * CH + c0 + lcol];
            float xs[4] = {xv.x, xv.y, xv.z, xv.w};
#pragma unroll
            for (int j = 0; j < 4; j++) {
                uint32_t hb = f2tf(xs[j]);
                Xhi[m * 36 + lcol + j] = __uint_as_float(hb);
                Xlo[m * 36 + lcol + j] =
                    __uint_as_float(f2tf(xs[j] - __uint_as_float(hb)));
            }
        }
#pragma unroll
        for (int p = 0; p < 2; p++) {
            int n = lrow + p * 32;
            float4 wv = *(const float4*)&W[(size_t)(n0 + n) * CH + c0 + lcol];
            float ws[4] = {wv.x, wv.y, wv.z, wv.w};
#pragma unroll
            for (int j = 0; j < 4; j++) {
                uint32_t hb = f2tf(ws[j]);
                Whi[n * 36 + lcol + j] = __uint_as_float(hb);
                Wlo[n * 36 + lcol + j] =
                    __uint_as_float(f2tf(ws[j] - __uint_as_float(hb)));
            }
        }
        __syncthreads();

#pragma unroll
        for (int ks = 0; ks < 4; ks++) {
            const int k = ks * 8 + c;
            uint32_t ahi[2][4], alo[2][4], bhi[4][2], blo[4][2];
#pragma unroll
            for (int mi = 0; mi < 2; mi++) {
                int mm = wm * 32 + mi * 16;
                ahi[mi][0] = __float_as_uint(Xhi[(mm + r) * 36 + k]);
                ahi[mi][1] = __float_as_uint(Xhi[(mm + r + 8) * 36 + k]);
                ahi[mi][2] = __float_as_uint(Xhi[(mm + r) * 36 + k + 4]);
                ahi[mi][3] = __float_as_uint(Xhi[(mm + r + 8) * 36 + k + 4]);
                alo[mi][0] = __float_as_uint(Xlo[(mm + r) * 36 + k]);
                alo[mi][1] = __float_as_uint(Xlo[(mm + r + 8) * 36 + k]);
                alo[mi][2] = __float_as_uint(Xlo[(mm + r) * 36 + k + 4]);
                alo[mi][3] = __float_as_uint(Xlo[(mm + r + 8) * 36 + k + 4]);
            }
#pragma unroll
            for (int f = 0; f < 4; f++) {
                int nn = wn * 32 + f * 8 + r;
                bhi[f][0] = __float_as_uint(Whi[nn * 36 + k]);
                bhi[f][1] = __float_as_uint(Whi[nn * 36 + k + 4]);
                blo[f][0] = __float_as_uint(Wlo[nn * 36 + k]);
                blo[f][1] = __float_as_uint(Wlo[nn * 36 + k + 4]);
            }
#pragma unroll
            for (int mi = 0; mi < 2; mi++)
#pragma unroll
                for (int f = 0; f < 4; f++) {
                    mma_tf32(acc[mi][f][0], acc[mi][f][1], acc[mi][f][2], acc[mi][f][3],
                             ahi[mi][0], ahi[mi][1], ahi[mi][2], ahi[mi][3],
                             bhi[f][0], bhi[f][1]);
                    mma_tf32(acc[mi][f][0], acc[mi][f][1], acc[mi][f][2], acc[mi][f][3],
                             ahi[mi][0], ahi[mi][1], ahi[mi][2], ahi[mi][3],
                             blo[f][0], blo[f][1]);
                    mma_tf32(acc[mi][f][0], acc[mi][f][1], acc[mi][f][2], acc[mi][f][3],
                             alo[mi][0], alo[mi][1], alo[mi][2], alo[mi][3],
                             bhi[f][0], bhi[f][1]);
                }
        }
    }

#pragma unroll
    for (int mi = 0; mi < 2; mi++)
#pragma unroll
        for (int f = 0; f < 4; f++) {
            int n = n0 + wn * 32 + f * 8 + 2 * c;
            float b0 = bias[n], b1 = bias[n + 1];
            int m = m0 + wm * 32 + mi * 16 + r;
            float2 o0 = make_float2(acc[mi][f][0] + b0, acc[mi][f][1] + b1);
            float2 o1 = make_float2(acc[mi][f][2] + b0, acc[mi][f][3] + b1);
            *(float2*)&Y[(size_t)m * CH + n] = o0;
            *(float2*)&Y[(size_t)(m + 8) * CH + n] = o1;
        }
}

// ---------------------------------------------------------------------------
// Fused attention, tf32 MMA.  256 thr = 8 warps, q-tile 128 (16 q per warp).
// K/V tiles shared by all 8 warps; per-warp Ps hi/lo.  TK=64.
// smem (floats): Khi[96][72] Klo[96][72] Vs[96][68]
//                union{ Qst[96][136] | Pshi 8x16x68 ; Pslo 8x16x68 }
// ---------------------------------------------------------------------------
#define SM_KHI 0
#define SM_KLO (96*72)
#define SM_VS  (2*96*72)
#define SM_UN  (2*96*72 + 96*68)
#define SM_PLO (SM_UN + 8*16*68)
#define ATTN_SMEM_FLOATS (SM_UN + 2*8*16*68)   // 37760
#define ATTN_SMEM_BYTES  (ATTN_SMEM_FLOATS*4)  // 151040

__global__ __launch_bounds__(256, 1) void attn_mma(float* __restrict__ out)
{
    extern __shared__ float sm[];
    float* Khi  = sm + SM_KHI;
    float* Klo  = sm + SM_KLO;
    float* Vs   = sm + SM_VS;
    float* Qst  = sm + SM_UN;
    float* Pshi = sm + SM_UN  + (threadIdx.x >> 5) * (16 * 68);
    float* Pslo = sm + SM_PLO + (threadIdx.x >> 5) * (16 * 68);

    const int tid  = threadIdx.x;
    const int lane = tid & 31;
    const int w    = tid >> 5;             // 0..7
    const int r    = lane >> 2;
    const int c    = lane & 3;
    const int q0   = blockIdx.x * 128;
    const size_t base = (size_t)blockIdx.z * (SEQ * CH) + (size_t)blockIdx.y * (HDIM * SEQ);

    // stage Q tile [96][128] -> smem stride 136
    for (int idx = tid; idx < HDIM * 128; idx += 256) {
        int d = idx >> 7, q = idx & 127;
        Qst[d * 136 + q] = g_Q[base + (size_t)d * SEQ + q0 + q];
    }
    __syncthreads();

    // Q fragments hi/lo -> registers (warp w owns q rows w*16..w*16+15)
    uint32_t qhi[12][4], qlo[12][4];
    const int qm = w * 16 + r;
#pragma unroll
    for (int ks = 0; ks < 12; ks++) {
        float v0 = Qst[(8 * ks + c) * 136 + qm];
        float v1 = Qst[(8 * ks + c) * 136 + qm + 8];
        float v2 = Qst[(8 * ks + c + 4) * 136 + qm];
        float v3 = Qst[(8 * ks + c + 4) * 136 + qm + 8];
        qhi[ks][0] = f2tf(v0); qlo[ks][0] = f2tf(v0 - __uint_as_float(qhi[ks][0]));
        qhi[ks][1] = f2tf(v1); qlo[ks][1] = f2tf(v1 - __uint_as_float(qhi[ks][1]));
        qhi[ks][2] = f2tf(v2); qlo[ks][2] = f2tf(v2 - __uint_as_float(qhi[ks][2]));
        qhi[ks][3] = f2tf(v3); qlo[ks][3] = f2tf(v3 - __uint_as_float(qhi[ks][3]));
    }

    float O[12][4];
#pragma unroll
    for (int f = 0; f < 12; f++)
#pragma unroll
        for (int j = 0; j < 4; j++) O[f][j] = 0.f;
    float mrow[2] = {-1e30f, -1e30f};
    float lrow[2] = {0.f, 0.f};

    for (int t0 = 0; t0 < SEQ; t0 += 64) {
        __syncthreads();   // prior iter's K/V reads (and Q-frag reads, iter 0) done
        for (int idx = tid; idx < HDIM * 64; idx += 256) {
            int d = idx >> 6, k = idx & 63;
            float kv = g_K[base + (size_t)d * SEQ + t0 + k];
            uint32_t kh = f2tf(kv);
            Khi[d * 72 + k] = __uint_as_float(kh);
            Klo[d * 72 + k] = __uint_as_float(f2tf(kv - __uint_as_float(kh)));
            Vs[d * 68 + k]  = __uint_as_float(f2tf(g_V[base + (size_t)d * SEQ + t0 + k]));
        }
        __syncthreads();

        // ---- S = Q^T K (3x tf32) ----
        float S[8][4];
#pragma unroll
        for (int f = 0; f < 8; f++)
#pragma unroll
            for (int j = 0; j < 4; j++) S[f][j] = 0.f;

#pragma unroll
        for (int ks = 0; ks < 12; ks++) {
            const int kb = (8 * ks + c) * 72 + r;
#pragma unroll
            for (int f = 0; f < 8; f++) {
                uint32_t bh0 = __float_as_uint(Khi[kb + f * 8]);
                uint32_t bh1 = __float_as_uint(Khi[kb + f * 8 + 4 * 72]);
                uint32_t bl0 = __float_as_uint(Klo[kb + f * 8]);
                uint32_t bl1 = __float_as_uint(Klo[kb + f * 8 + 4 * 72]);
                mma_tf32(S[f][0], S[f][1], S[f][2], S[f][3],
                         qhi[ks][0], qhi[ks][1], qhi[ks][2], qhi[ks][3], bh0, bh1);
                mma_tf32(S[f][0], S[f][1], S[f][2], S[f][3],
                         qhi[ks][0], qhi[ks][1], qhi[ks][2], qhi[ks][3], bl0, bl1);
                mma_tf32(S[f][0], S[f][1], S[f][2], S[f][3],
                         qlo[ks][0], qlo[ks][1], qlo[ks][2], qlo[ks][3], bh0, bh1);
            }
        }

        // ---- online softmax (rows r, r+8 of this warp's 16-q block) ----
#pragma unroll
        for (int half = 0; half < 2; half++) {
            float mx = -1e30f;
#pragma unroll
            for (int f = 0; f < 8; f++)
                mx = fmaxf(mx, fmaxf(S[f][2 * half], S[f][2 * half + 1]));
            mx = fmaxf(mx, __shfl_xor_sync(0xFFFFFFFFu, mx, 1));
            mx = fmaxf(mx, __shfl_xor_sync(0xFFFFFFFFu, mx, 2));
            float mnew = fmaxf(mrow[half], mx);
            float al = __expf(mrow[half] - mnew);
            float rs = 0.f;
#pragma unroll
            for (int f = 0; f < 8; f++) {
                float p0 = __expf(S[f][2 * half] - mnew);
                float p1 = __expf(S[f][2 * half + 1] - mnew);
                rs += p0 + p1;
                uint32_t h0 = f2tf(p0), h1 = f2tf(p1);
                float l0 = p0 - __uint_as_float(h0);
                float l1 = p1 - __uint_as_float(h1);
                *(float2*)&Pshi[(r + 8 * half) * 68 + f * 8 + 2 * c] =
                    make_float2(__uint_as_float(h0), __uint_as_float(h1));
                *(float2*)&Pslo[(r + 8 * half) * 68 + f * 8 + 2 * c] =
                    make_float2(__uint_as_float(f2tf(l0)), __uint_as_float(f2tf(l1)));
            }
            rs += __shfl_xor_sync(0xFFFFFFFFu, rs, 1);
            rs += __shfl_xor_sync(0xFFFFFFFFu, rs, 2);
            lrow[half] = lrow[half] * al + rs;
            mrow[half] = mnew;
#pragma unroll
            for (int f = 0; f < 12; f++) {
                O[f][2 * half]     *= al;
                O[f][2 * half + 1] *= al;
            }
        }
        __syncwarp();

        // ---- O += (Phi + Plo) @ V^T ----
#pragma unroll
        for (int ks = 0; ks < 8; ks++) {
            uint32_t a0 = __float_as_uint(Pshi[r * 68 + ks * 8 + c]);
            uint32_t a1 = __float_as_uint(Pshi[(r + 8) * 68 + ks * 8 + c]);
            uint32_t a2 = __float_as_uint(Pshi[r * 68 + ks * 8 + c + 4]);
            uint32_t a3 = __float_as_uint(Pshi[(r + 8) * 68 + ks * 8 + c + 4]);
            uint32_t e0 = __float_as_uint(Pslo[r * 68 + ks * 8 + c]);
            uint32_t e1 = __float_as_uint(Pslo[(r + 8) * 68 + ks * 8 + c]);
            uint32_t e2 = __float_as_uint(Pslo[r * 68 + ks * 8 + c + 4]);
            uint32_t e3 = __float_as_uint(Pslo[(r + 8) * 68 + ks * 8 + c + 4]);
#pragma unroll
            for (int f = 0; f < 12; f++) {
                uint32_t b0 = __float_as_uint(Vs[(f * 8 + r) * 68 + ks * 8 + c]);
                uint32_t b1 = __float_as_uint(Vs[(f * 8 + r) * 68 + ks * 8 + c + 4]);
                mma_tf32(O[f][0], O[f][1], O[f][2], O[f][3], a0, a1, a2, a3, b0, b1);
                mma_tf32(O[f][0], O[f][1], O[f][2], O[f][3], e0, e1, e2, e3, b0, b1);
            }
        }
        __syncwarp();
    }

    float inv0 = 1.f / lrow[0];
    float inv1 = 1.f / lrow[1];
#pragma unroll
    for (int f = 0; f < 12; f++) {
        int d0 = f * 8 + 2 * c;
        int qa = q0 + w * 16 + r;
        out[base + (size_t)d0 * SEQ + qa]           = O[f][0] * inv0;
        out[base + (size_t)(d0 + 1) * SEQ + qa]     = O[f][1] * inv0;
        out[base + (size_t)d0 * SEQ + qa + 8]       = O[f][2] * inv1;
        out[base + (size_t)(d0 + 1) * SEQ + qa + 8] = O[f][3] * inv1;
    }
}

// ---------------------------------------------------------------------------
extern "C" void kernel_launch(void* const* d_in, const int* in_sizes, int n_in,
                              void* d_out, int out_size)
{
    (void)in_sizes; (void)n_in; (void)out_size;
    const float* x1 = (const float*)d_in[0];
    const float* x2 = (const float*)d_in[1];
    const float* Wq = (const float*)d_in[2];
    const float* bq = (const float*)d_in[3];
    const float* Wk = (const float*)d_in[4];
    const float* bk = (const float*)d_in[5];
    const float* Wv = (const float*)d_in[6];
    const float* bv = (const float*)d_in[7];
    float* out = (float*)d_out;

    cudaFuncSetAttribute(proj_mma, cudaFuncAttributeMaxDynamicSharedMemorySize,
                         PROJ_SMEM_BYTES);
    cudaFuncSetAttribute(attn_mma, cudaFuncAttributeMaxDynamicSharedMemorySize,
                         ATTN_SMEM_BYTES);

    proj_mma<<<dim3(9, 64, 3), 256, PROJ_SMEM_BYTES>>>(
        x1, x2, Wq, bq, Wk, bk, Wv, bv);
    attn_mma<<<dim3(8, NHEAD, NB), 256, ATTN_SMEM_BYTES>>>(out);
}

// round 5
// speedup vs baseline: 2.0358x; 1.0925x over previous
#include <cuda_runtime.h>
#include <cstdint>

#define NB    8
#define SEQ   1024
#define CH    576
#define NHEAD 6
#define HDIM  96

__device__ float g_Q[NB*SEQ*CH];
__device__ float g_K[NB*SEQ*CH];
__device__ float g_V[NB*SEQ*CH];

__device__ __forceinline__ uint32_t f2tf(float x) {
    uint32_t u;
    asm("cvt.rna.tf32.f32 %0, %1;" : "=r"(u) : "f"(x));
    return u;
}

__device__ __forceinline__ void mma_tf32(float& d0, float& d1, float& d2, float& d3,
                                         uint32_t a0, uint32_t a1, uint32_t a2, uint32_t a3,
                                         uint32_t b0, uint32_t b1) {
    asm volatile(
        "mma.sync.aligned.m16n8k8.row.col.f32.tf32.tf32.f32 "
        "{%0,%1,%2,%3},{%4,%5,%6,%7},{%8,%9},{%0,%1,%2,%3};"
        : "+f"(d0), "+f"(d1), "+f"(d2), "+f"(d3)
        : "r"(a0), "r"(a1), "r"(a2), "r"(a3), "r"(b0), "r"(b1));
}

// ---------------------------------------------------------------------------
// Projection: Y = X @ W^T + bias.  SPLIT: 3x-tf32 (Q,K via blockIdx.z 0/1);
// !SPLIT: single tf32 (V).  Scratch output resolved in device code.
// ---------------------------------------------------------------------------
#define PROJ_SMEM_SPLIT ((2*128*36 + 2*64*36) * 4)
#define PROJ_SMEM_ONE   ((128*36 + 64*36) * 4)

template<bool SPLIT>
__global__ __launch_bounds__(256) void proj_mma(
    const float* __restrict__ x1, const float* __restrict__ x2,
    const float* __restrict__ Wq, const float* __restrict__ bq,
    const float* __restrict__ Wk, const float* __restrict__ bk,
    const float* __restrict__ Wv, const float* __restrict__ bv)
{
    const int which = SPLIT ? blockIdx.z : 2;
    const float* X    = (which == 0) ? x1 : x2;
    const float* W    = (which == 0) ? Wq : (which == 1) ? Wk : Wv;
    const float* bias = (which == 0) ? bq : (which == 1) ? bk : bv;
    float*       Y    = (which == 0) ? g_Q : (which == 1) ? g_K : g_V;

    extern __shared__ float sp[];
    float* Xhi = sp;
    float* Whi = sp + 128*36;
    float* Xlo = sp + 128*36 + 64*36;
    float* Wlo = sp + 2*128*36 + 64*36;

    const int tid  = threadIdx.x;
    const int lane = tid & 31;
    const int w    = tid >> 5;
    const int wm   = w & 3, wn = w >> 2;
    const int r    = lane >> 2, c = lane & 3;
    const int n0   = blockIdx.x * 64;
    const int m0   = blockIdx.y * 128;

    float acc[2][4][4];
#pragma unroll
    for (int mi = 0; mi < 2; mi++)
#pragma unroll
        for (int f = 0; f < 4; f++)
#pragma unroll
            for (int j = 0; j < 4; j++) acc[mi][f][j] = 0.f;

    const int lrow = tid >> 3;
    const int lcol = (tid & 7) * 4;

    for (int c0 = 0; c0 < CH; c0 += 32) {
        __syncthreads();
#pragma unroll
        for (int p = 0; p < 4; p++) {
            int m = lrow + p * 32;
            float4 xv = *(const float4*)&X[(size_t)(m0 + m) * CH + c0 + lcol];
            float xs[4] = {xv.x, xv.y, xv.z, xv.w};
#pragma unroll
            for (int j = 0; j < 4; j++) {
                uint32_t hb = f2tf(xs[j]);
                Xhi[m * 36 + lcol + j] = __uint_as_float(hb);
                if (SPLIT)
                    Xlo[m * 36 + lcol + j] =
                        __uint_as_float(f2tf(xs[j] - __uint_as_float(hb)));
            }
        }
#pragma unroll
        for (int p = 0; p < 2; p++) {
            int n = lrow + p * 32;
            float4 wv = *(const float4*)&W[(size_t)(n0 + n) * CH + c0 + lcol];
            float ws[4] = {wv.x, wv.y, wv.z, wv.w};
#pragma unroll
            for (int j = 0; j < 4; j++) {
                uint32_t hb = f2tf(ws[j]);
                Whi[n * 36 + lcol + j] = __uint_as_float(hb);
                if (SPLIT)
                    Wlo[n * 36 + lcol + j] =
                        __uint_as_float(f2tf(ws[j] - __uint_as_float(hb)));
            }
        }
        __syncthreads();

#pragma unroll
        for (int ks = 0; ks < 4; ks++) {
            const int k = ks * 8 + c;
            uint32_t ahi[2][4], alo[2][4], bhi[4][2], blo[4][2];
#pragma unroll
            for (int mi = 0; mi < 2; mi++) {
                int mm = wm * 32 + mi * 16;
                ahi[mi][0] = __float_as_uint(Xhi[(mm + r) * 36 + k]);
                ahi[mi][1] = __float_as_uint(Xhi[(mm + r + 8) * 36 + k]);
                ahi[mi][2] = __float_as_uint(Xhi[(mm + r) * 36 + k + 4]);
                ahi[mi][3] = __float_as_uint(Xhi[(mm + r + 8) * 36 + k + 4]);
                if (SPLIT) {
                    alo[mi][0] = __float_as_uint(Xlo[(mm + r) * 36 + k]);
                    alo[mi][1] = __float_as_uint(Xlo[(mm + r + 8) * 36 + k]);
                    alo[mi][2] = __float_as_uint(Xlo[(mm + r) * 36 + k + 4]);
                    alo[mi][3] = __float_as_uint(Xlo[(mm + r + 8) * 36 + k + 4]);
                }
            }
#pragma unroll
            for (int f = 0; f < 4; f++) {
                int nn = wn * 32 + f * 8 + r;
                bhi[f][0] = __float_as_uint(Whi[nn * 36 + k]);
                bhi[f][1] = __float_as_uint(Whi[nn * 36 + k + 4]);
                if (SPLIT) {
                    blo[f][0] = __float_as_uint(Wlo[nn * 36 + k]);
                    blo[f][1] = __float_as_uint(Wlo[nn * 36 + k + 4]);
                }
            }
#pragma unroll
            for (int mi = 0; mi < 2; mi++)
#pragma unroll
                for (int f = 0; f < 4; f++) {
                    mma_tf32(acc[mi][f][0], acc[mi][f][1], acc[mi][f][2], acc[mi][f][3],
                             ahi[mi][0], ahi[mi][1], ahi[mi][2], ahi[mi][3],
                             bhi[f][0], bhi[f][1]);
                    if (SPLIT) {
                        mma_tf32(acc[mi][f][0], acc[mi][f][1], acc[mi][f][2], acc[mi][f][3],
                                 ahi[mi][0], ahi[mi][1], ahi[mi][2], ahi[mi][3],
                                 blo[f][0], blo[f][1]);
                        mma_tf32(acc[mi][f][0], acc[mi][f][1], acc[mi][f][2], acc[mi][f][3],
                                 alo[mi][0], alo[mi][1], alo[mi][2], alo[mi][3],
                                 bhi[f][0], bhi[f][1]);
                    }
                }
        }
    }

#pragma unroll
    for (int mi = 0; mi < 2; mi++)
#pragma unroll
        for (int f = 0; f < 4; f++) {
            int n = n0 + wn * 32 + f * 8 + 2 * c;
            float b0 = bias[n], b1 = bias[n + 1];
            int m = m0 + wm * 32 + mi * 16 + r;
            float2 o0 = make_float2(acc[mi][f][0] + b0, acc[mi][f][1] + b1);
            float2 o1 = make_float2(acc[mi][f][2] + b0, acc[mi][f][3] + b1);
            *(float2*)&Y[(size_t)m * CH + n] = o0;
            *(float2*)&Y[(size_t)(m + 8) * CH + n] = o1;
        }
}

// ---------------------------------------------------------------------------
// Fused attention. 256 thr = 8 warps, q-tile 128 (16 q/warp), TK=64.
// K tiles in f-contiguous layout: Khi[d*104 + (k&7)*12 + (k>>3)] so each
// lane's 8 B-fragment words per d-row are 2x LDS.128.  PV: P single tf32.
// smem: Khi[96*104] Klo[96*104] Vs[96*68] union{Qst[96*136] | Pshi 8*16*68}
// ---------------------------------------------------------------------------
#define KSTR 104
#define SM_KHI 0
#define SM_KLO (96*KSTR)
#define SM_VS  (2*96*KSTR)
#define SM_UN  (2*96*KSTR + 96*68)
#define ATTN_SMEM_FLOATS (SM_UN + 96*136)      // 39552
#define ATTN_SMEM_BYTES  (ATTN_SMEM_FLOATS*4)  // 158208

__global__ __launch_bounds__(256, 1) void attn_mma(float* __restrict__ out)
{
    extern __shared__ float sm[];
    float* Khi  = sm + SM_KHI;
    float* Klo  = sm + SM_KLO;
    float* Vs   = sm + SM_VS;
    float* Qst  = sm + SM_UN;
    float* Pshi = sm + SM_UN + (threadIdx.x >> 5) * (16 * 68);

    const int tid  = threadIdx.x;
    const int lane = tid & 31;
    const int w    = tid >> 5;
    const int r    = lane >> 2;
    const int c    = lane & 3;
    const int q0   = blockIdx.x * 128;
    const size_t base = (size_t)blockIdx.z * (SEQ * CH) + (size_t)blockIdx.y * (HDIM * SEQ);

    for (int idx = tid; idx < HDIM * 128; idx += 256) {
        int d = idx >> 7, q = idx & 127;
        Qst[d * 136 + q] = g_Q[base + (size_t)d * SEQ + q0 + q];
    }
    __syncthreads();

    uint32_t qhi[12][4], qlo[12][4];
    const int qm = w * 16 + r;
#pragma unroll
    for (int ks = 0; ks < 12; ks++) {
        float v0 = Qst[(8 * ks + c) * 136 + qm];
        float v1 = Qst[(8 * ks + c) * 136 + qm + 8];
        float v2 = Qst[(8 * ks + c + 4) * 136 + qm];
        float v3 = Qst[(8 * ks + c + 4) * 136 + qm + 8];
        qhi[ks][0] = f2tf(v0); qlo[ks][0] = f2tf(v0 - __uint_as_float(qhi[ks][0]));
        qhi[ks][1] = f2tf(v1); qlo[ks][1] = f2tf(v1 - __uint_as_float(qhi[ks][1]));
        qhi[ks][2] = f2tf(v2); qlo[ks][2] = f2tf(v2 - __uint_as_float(qhi[ks][2]));
        qhi[ks][3] = f2tf(v3); qlo[ks][3] = f2tf(v3 - __uint_as_float(qhi[ks][3]));
    }

    float O[12][4];
#pragma unroll
    for (int f = 0; f < 12; f++)
#pragma unroll
        for (int j = 0; j < 4; j++) O[f][j] = 0.f;
    float mrow[2] = {-1e30f, -1e30f};
    float lrow[2] = {0.f, 0.f};

    for (int t0 = 0; t0 < SEQ; t0 += 64) {
        __syncthreads();
        for (int idx = tid; idx < HDIM * 64; idx += 256) {
            int d = idx >> 6, k = idx & 63;
            float kv = g_K[base + (size_t)d * SEQ + t0 + k];
            uint32_t kh = f2tf(kv);
            int slot = d * KSTR + (k & 7) * 12 + (k >> 3);
            Khi[slot] = __uint_as_float(kh);
            Klo[slot] = __uint_as_float(f2tf(kv - __uint_as_float(kh)));
            Vs[d * 68 + k] = __uint_as_float(f2tf(g_V[base + (size_t)d * SEQ + t0 + k]));
        }
        __syncthreads();

        // ---- S = Q^T K (3x tf32), vectorized fragment loads ----
        float S[8][4];
#pragma unroll
        for (int f = 0; f < 8; f++)
#pragma unroll
            for (int j = 0; j < 4; j++) S[f][j] = 0.f;

#pragma unroll
        for (int ks = 0; ks < 12; ks++) {
            const int d0 = (8 * ks + c) * KSTR + r * 12;
            const int d1 = (8 * ks + c + 4) * KSTR + r * 12;
            float4 H0a = *(const float4*)&Khi[d0];
            float4 H0b = *(const float4*)&Khi[d0 + 4];
            float4 H1a = *(const float4*)&Khi[d1];
            float4 H1b = *(const float4*)&Khi[d1 + 4];
            float4 L0a = *(const float4*)&Klo[d0];
            float4 L0b = *(const float4*)&Klo[d0 + 4];
            float4 L1a = *(const float4*)&Klo[d1];
            float4 L1b = *(const float4*)&Klo[d1 + 4];
            uint32_t bh0[8] = {__float_as_uint(H0a.x), __float_as_uint(H0a.y),
                               __float_as_uint(H0a.z), __float_as_uint(H0a.w),
                               __float_as_uint(H0b.x), __float_as_uint(H0b.y),
                               __float_as_uint(H0b.z), __float_as_uint(H0b.w)};
            uint32_t bh1[8] = {__float_as_uint(H1a.x), __float_as_uint(H1a.y),
                               __float_as_uint(H1a.z), __float_as_uint(H1a.w),
                               __float_as_uint(H1b.x), __float_as_uint(H1b.y),
                               __float_as_uint(H1b.z), __float_as_uint(H1b.w)};
            uint32_t bl0[8] = {__float_as_uint(L0a.x), __float_as_uint(L0a.y),
                               __float_as_uint(L0a.z), __float_as_uint(L0a.w),
                               __float_as_uint(L0b.x), __float_as_uint(L0b.y),
                               __float_as_uint(L0b.z), __float_as_uint(L0b.w)};
            uint32_t bl1[8] = {__float_as_uint(L1a.x), __float_as_uint(L1a.y),
                               __float_as_uint(L1a.z), __float_as_uint(L1a.w),
                               __float_as_uint(L1b.x), __float_as_uint(L1b.y),
                               __float_as_uint(L1b.z), __float_as_uint(L1b.w)};
#pragma unroll
            for (int f = 0; f < 8; f++) {
                mma_tf32(S[f][0], S[f][1], S[f][2], S[f][3],
                         qhi[ks][0], qhi[ks][1], qhi[ks][2], qhi[ks][3],
                         bh0[f], bh1[f]);
                mma_tf32(S[f][0], S[f][1], S[f][2], S[f][3],
                         qhi[ks][0], qhi[ks][1], qhi[ks][2], qhi[ks][3],
                         bl0[f], bl1[f]);
                mma_tf32(S[f][0], S[f][1], S[f][2], S[f][3],
                         qlo[ks][0], qlo[ks][1], qlo[ks][2], qlo[ks][3],
                         bh0[f], bh1[f]);
            }
        }

        // ---- online softmax ----
#pragma unroll
        for (int half = 0; half < 2; half++) {
            float mx = -1e30f;
#pragma unroll
            for (int f = 0; f < 8; f++)
                mx = fmaxf(mx, fmaxf(S[f][2 * half], S[f][2 * half + 1]));
            mx = fmaxf(mx, __shfl_xor_sync(0xFFFFFFFFu, mx, 1));
            mx = fmaxf(mx, __shfl_xor_sync(0xFFFFFFFFu, mx, 2));
            float mnew = fmaxf(mrow[half], mx);
            float al = __expf(mrow[half] - mnew);
            float rs = 0.f;
#pragma unroll
            for (int f = 0; f < 8; f++) {
                float p0 = __expf(S[f][2 * half] - mnew);
                float p1 = __expf(S[f][2 * half + 1] - mnew);
                rs += p0 + p1;
                *(float2*)&Pshi[(r + 8 * half) * 68 + f * 8 + 2 * c] =
                    make_float2(__uint_as_float(f2tf(p0)), __uint_as_float(f2tf(p1)));
            }
            rs += __shfl_xor_sync(0xFFFFFFFFu, rs, 1);
            rs += __shfl_xor_sync(0xFFFFFFFFu, rs, 2);
            lrow[half] = lrow[half] * al + rs;
            mrow[half] = mnew;
#pragma unroll
            for (int f = 0; f < 12; f++) {
                O[f][2 * half]     *= al;
                O[f][2 * half + 1] *= al;
            }
        }
        __syncwarp();

        // ---- O += P @ V^T (single tf32) ----
#pragma unroll
        for (int ks = 0; ks < 8; ks++) {
            uint32_t a0 = __float_as_uint(Pshi[r * 68 + ks * 8 + c]);
            uint32_t a1 = __float_as_uint(Pshi[(r + 8) * 68 + ks * 8 + c]);
            uint32_t a2 = __float_as_uint(Pshi[r * 68 + ks * 8 + c + 4]);
            uint32_t a3 = __float_as_uint(Pshi[(r + 8) * 68 + ks * 8 + c + 4]);
#pragma unroll
            for (int f = 0; f < 12; f++) {
                uint32_t b0 = __float_as_uint(Vs[(f * 8 + r) * 68 + ks * 8 + c]);
                uint32_t b1 = __float_as_uint(Vs[(f * 8 + r) * 68 + ks * 8 + c + 4]);
                mma_tf32(O[f][0], O[f][1], O[f][2], O[f][3], a0, a1, a2, a3, b0, b1);
            }
        }
        __syncwarp();
    }

    float inv0 = 1.f / lrow[0];
    float inv1 = 1.f / lrow[1];
#pragma unroll
    for (int f = 0; f < 12; f++) {
        int d0 = f * 8 + 2 * c;
        int qa = q0 + w * 16 + r;
        out[base + (size_t)d0 * SEQ + qa]           = O[f][0] * inv0;
        out[base + (size_t)(d0 + 1) * SEQ + qa]     = O[f][1] * inv0;
        out[base + (size_t)d0 * SEQ + qa + 8]       = O[f][2] * inv1;
        out[base + (size_t)(d0 + 1) * SEQ + qa + 8] = O[f][3] * inv1;
    }
}

// ---------------------------------------------------------------------------
extern "C" void kernel_launch(void* const* d_in, const int* in_sizes, int n_in,
                              void* d_out, int out_size)
{
    (void)in_sizes; (void)n_in; (void)out_size;
    const float* x1 = (const float*)d_in[0];
    const float* x2 = (const float*)d_in[1];
    const float* Wq = (const float*)d_in[2];
    const float* bq = (const float*)d_in[3];
    const float* Wk = (const float*)d_in[4];
    const float* bk = (const float*)d_in[5];
    const float* Wv = (const float*)d_in[6];
    const float* bv = (const float*)d_in[7];
    float* out = (float*)d_out;

    cudaFuncSetAttribute(proj_mma<true>, cudaFuncAttributeMaxDynamicSharedMemorySize,
                         PROJ_SMEM_SPLIT);
    cudaFuncSetAttribute(proj_mma<false>, cudaFuncAttributeMaxDynamicSharedMemorySize,
                         PROJ_SMEM_ONE);
    cudaFuncSetAttribute(attn_mma, cudaFuncAttributeMaxDynamicSharedMemorySize,
                         ATTN_SMEM_BYTES);

    proj_mma<true><<<dim3(9, 64, 2), 256, PROJ_SMEM_SPLIT>>>(
        x1, x2, Wq, bq, Wk, bk, Wv, bv);
    proj_mma<false><<<dim3(9, 64, 1), 256, PROJ_SMEM_ONE>>>(
        x1, x2, Wq, bq, Wk, bk, Wv, bv);
    attn_mma<<<dim3(8, NHEAD, NB), 256, ATTN_SMEM_BYTES>>>(out);
}

// round 6
// speedup vs baseline: 2.0701x; 1.0168x over previous
#include <cuda_runtime.h>
#include <cstdint>

#define NB    8
#define SEQ   1024
#define CH    576
#define NHEAD 6
#define HDIM  96

__device__ float g_Q[NB*SEQ*CH];
__device__ float g_K[NB*SEQ*CH];
__device__ float g_V[NB*SEQ*CH];

__device__ __forceinline__ uint32_t f2tf(float x) {
    uint32_t u;
    asm("cvt.rna.tf32.f32 %0, %1;" : "=r"(u) : "f"(x));
    return u;
}

__device__ __forceinline__ void mma_tf32(float& d0, float& d1, float& d2, float& d3,
                                         uint32_t a0, uint32_t a1, uint32_t a2, uint32_t a3,
                                         uint32_t b0, uint32_t b1) {
    asm volatile(
        "mma.sync.aligned.m16n8k8.row.col.f32.tf32.tf32.f32 "
        "{%0,%1,%2,%3},{%4,%5,%6,%7},{%8,%9},{%0,%1,%2,%3};"
        : "+f"(d0), "+f"(d1), "+f"(d2), "+f"(d3)
        : "r"(a0), "r"(a1), "r"(a2), "r"(a3), "r"(b0), "r"(b1));
}

// ---------------------------------------------------------------------------
// Projection: Y = X @ W^T + bias.  SPLIT: 3x-tf32 (Q,K); !SPLIT: 1x tf32 (V).
// ---------------------------------------------------------------------------
#define PROJ_SMEM_SPLIT ((2*128*36 + 2*64*36) * 4)
#define PROJ_SMEM_ONE   ((128*36 + 64*36) * 4)

template<bool SPLIT>
__global__ __launch_bounds__(256) void proj_mma(
    const float* __restrict__ x1, const float* __restrict__ x2,
    const float* __restrict__ Wq, const float* __restrict__ bq,
    const float* __restrict__ Wk, const float* __restrict__ bk,
    const float* __restrict__ Wv, const float* __restrict__ bv)
{
    const int which = SPLIT ? blockIdx.z : 2;
    const float* X    = (which == 0) ? x1 : x2;
    const float* W    = (which == 0) ? Wq : (which == 1) ? Wk : Wv;
    const float* bias = (which == 0) ? bq : (which == 1) ? bk : bv;
    float*       Y    = (which == 0) ? g_Q : (which == 1) ? g_K : g_V;

    extern __shared__ float sp[];
    float* Xhi = sp;
    float* Whi = sp + 128*36;
    float* Xlo = sp + 128*36 + 64*36;
    float* Wlo = sp + 2*128*36 + 64*36;

    const int tid  = threadIdx.x;
    const int lane = tid & 31;
    const int w    = tid >> 5;
    const int wm   = w & 3, wn = w >> 2;
    const int r    = lane >> 2, c = lane & 3;
    const int n0   = blockIdx.x * 64;
    const int m0   = blockIdx.y * 128;

    float acc[2][4][4];
#pragma unroll
    for (int mi = 0; mi < 2; mi++)
#pragma unroll
        for (int f = 0; f < 4; f++)
#pragma unroll
            for (int j = 0; j < 4; j++) acc[mi][f][j] = 0.f;

    const int lrow = tid >> 3;
    const int lcol = (tid & 7) * 4;

    for (int c0 = 0; c0 < CH; c0 += 32) {
        __syncthreads();
#pragma unroll
        for (int p = 0; p < 4; p++) {
            int m = lrow + p * 32;
            float4 xv = *(const float4*)&X[(size_t)(m0 + m) * CH + c0 + lcol];
            float xs[4] = {xv.x, xv.y, xv.z, xv.w};
#pragma unroll
            for (int j = 0; j < 4; j++) {
                uint32_t hb = f2tf(xs[j]);
                Xhi[m * 36 + lcol + j] = __uint_as_float(hb);
                if (SPLIT)
                    Xlo[m * 36 + lcol + j] =
                        __uint_as_float(f2tf(xs[j] - __uint_as_float(hb)));
            }
        }
#pragma unroll
        for (int p = 0; p < 2; p++) {
            int n = lrow + p * 32;
            float4 wv = *(const float4*)&W[(size_t)(n0 + n) * CH + c0 + lcol];
            float ws[4] = {wv.x, wv.y, wv.z, wv.w};
#pragma unroll
            for (int j = 0; j < 4; j++) {
                uint32_t hb = f2tf(ws[j]);
                Whi[n * 36 + lcol + j] = __uint_as_float(hb);
                if (SPLIT)
                    Wlo[n * 36 + lcol + j] =
                        __uint_as_float(f2tf(ws[j] - __uint_as_float(hb)));
            }
        }
        __syncthreads();

#pragma unroll
        for (int ks = 0; ks < 4; ks++) {
            const int k = ks * 8 + c;
            uint32_t ahi[2][4], alo[2][4], bhi[4][2], blo[4][2];
#pragma unroll
            for (int mi = 0; mi < 2; mi++) {
                int mm = wm * 32 + mi * 16;
                ahi[mi][0] = __float_as_uint(Xhi[(mm + r) * 36 + k]);
                ahi[mi][1] = __float_as_uint(Xhi[(mm + r + 8) * 36 + k]);
                ahi[mi][2] = __float_as_uint(Xhi[(mm + r) * 36 + k + 4]);
                ahi[mi][3] = __float_as_uint(Xhi[(mm + r + 8) * 36 + k + 4]);
                if (SPLIT) {
                    alo[mi][0] = __float_as_uint(Xlo[(mm + r) * 36 + k]);
                    alo[mi][1] = __float_as_uint(Xlo[(mm + r + 8) * 36 + k]);
                    alo[mi][2] = __float_as_uint(Xlo[(mm + r) * 36 + k + 4]);
                    alo[mi][3] = __float_as_uint(Xlo[(mm + r + 8) * 36 + k + 4]);
                }
            }
#pragma unroll
            for (int f = 0; f < 4; f++) {
                int nn = wn * 32 + f * 8 + r;
                bhi[f][0] = __float_as_uint(Whi[nn * 36 + k]);
                bhi[f][1] = __float_as_uint(Whi[nn * 36 + k + 4]);
                if (SPLIT) {
                    blo[f][0] = __float_as_uint(Wlo[nn * 36 + k]);
                    blo[f][1] = __float_as_uint(Wlo[nn * 36 + k + 4]);
                }
            }
#pragma unroll
            for (int mi = 0; mi < 2; mi++)
#pragma unroll
                for (int f = 0; f < 4; f++) {
                    mma_tf32(acc[mi][f][0], acc[mi][f][1], acc[mi][f][2], acc[mi][f][3],
                             ahi[mi][0], ahi[mi][1], ahi[mi][2], ahi[mi][3],
                             bhi[f][0], bhi[f][1]);
                    if (SPLIT) {
                        mma_tf32(acc[mi][f][0], acc[mi][f][1], acc[mi][f][2], acc[mi][f][3],
                                 ahi[mi][0], ahi[mi][1], ahi[mi][2], ahi[mi][3],
                                 blo[f][0], blo[f][1]);
                        mma_tf32(acc[mi][f][0], acc[mi][f][1], acc[mi][f][2], acc[mi][f][3],
                                 alo[mi][0], alo[mi][1], alo[mi][2], alo[mi][3],
                                 bhi[f][0], bhi[f][1]);
                    }
                }
        }
    }

#pragma unroll
    for (int mi = 0; mi < 2; mi++)
#pragma unroll
        for (int f = 0; f < 4; f++) {
            int n = n0 + wn * 32 + f * 8 + 2 * c;
            float b0 = bias[n], b1 = bias[n + 1];
            int m = m0 + wm * 32 + mi * 16 + r;
            float2 o0 = make_float2(acc[mi][f][0] + b0, acc[mi][f][1] + b1);
            float2 o1 = make_float2(acc[mi][f][2] + b0, acc[mi][f][3] + b1);
            *(float2*)&Y[(size_t)m * CH + n] = o0;
            *(float2*)&Y[(size_t)(m + 8) * CH + n] = o1;
        }
}

// ---------------------------------------------------------------------------
// Fused attention. 256 thr = 8 warps, q-tile 128 (16 q/warp), TK=64.
// K in f-contiguous layout (2x LDS.128 per d-row per lane).
// Q-lo fragments live in dedicated smem (1 LDS.128/ks), NOT registers,
// to keep reg demand < 255 (R5 was spilling at the 255 clamp).
// smem: Khi[96*104] Klo[96*104] Vs[96*68] QLO[8*12*128]
//       union{ Qst[96*136] | Pshi 8*16*68 }
// ---------------------------------------------------------------------------
#define KSTR 104
#define SM_KHI 0
#define SM_KLO (96*KSTR)
#define SM_VS  (2*96*KSTR)
#define SM_QLO (2*96*KSTR + 96*68)
#define SM_UN  (SM_QLO + 8*12*128)
#define ATTN_SMEM_FLOATS (SM_UN + 96*136)      // 51840
#define ATTN_SMEM_BYTES  (ATTN_SMEM_FLOATS*4)  // 207360

__global__ __launch_bounds__(256, 1) void attn_mma(float* __restrict__ out)
{
    extern __shared__ float sm[];
    float* Khi  = sm + SM_KHI;
    float* Klo  = sm + SM_KLO;
    float* Vs   = sm + SM_VS;
    float* QLO  = sm + SM_QLO + (threadIdx.x >> 5) * (12 * 128);
    float* Qst  = sm + SM_UN;
    float* Pshi = sm + SM_UN + (threadIdx.x >> 5) * (16 * 68);

    const int tid  = threadIdx.x;
    const int lane = tid & 31;
    const int w    = tid >> 5;
    const int r    = lane >> 2;
    const int c    = lane & 3;
    const int q0   = blockIdx.x * 128;
    const size_t base = (size_t)blockIdx.z * (SEQ * CH) + (size_t)blockIdx.y * (HDIM * SEQ);

    for (int idx = tid; idx < HDIM * 128; idx += 256) {
        int d = idx >> 7, q = idx & 127;
        Qst[d * 136 + q] = g_Q[base + (size_t)d * SEQ + q0 + q];
    }
    __syncthreads();

    // Q hi fragments -> registers; lo fragments -> per-warp smem (float4/lane)
    uint32_t qhi[12][4];
    const int qm = w * 16 + r;
#pragma unroll
    for (int ks = 0; ks < 12; ks++) {
        float v0 = Qst[(8 * ks + c) * 136 + qm];
        float v1 = Qst[(8 * ks + c) * 136 + qm + 8];
        float v2 = Qst[(8 * ks + c + 4) * 136 + qm];
        float v3 = Qst[(8 * ks + c + 4) * 136 + qm + 8];
        qhi[ks][0] = f2tf(v0);
        qhi[ks][1] = f2tf(v1);
        qhi[ks][2] = f2tf(v2);
        qhi[ks][3] = f2tf(v3);
        float4 lo;
        lo.x = __uint_as_float(f2tf(v0 - __uint_as_float(qhi[ks][0])));
        lo.y = __uint_as_float(f2tf(v1 - __uint_as_float(qhi[ks][1])));
        lo.z = __uint_as_float(f2tf(v2 - __uint_as_float(qhi[ks][2])));
        lo.w = __uint_as_float(f2tf(v3 - __uint_as_float(qhi[ks][3])));
        *(float4*)&QLO[ks * 128 + lane * 4] = lo;
    }
    __syncwarp();

    float O[12][4];
#pragma unroll
    for (int f = 0; f < 12; f++)
#pragma unroll
        for (int j = 0; j < 4; j++) O[f][j] = 0.f;
    float mrow[2] = {-1e30f, -1e30f};
    float lrow[2] = {0.f, 0.f};

    for (int t0 = 0; t0 < SEQ; t0 += 64) {
        __syncthreads();
        for (int idx = tid; idx < HDIM * 64; idx += 256) {
            int d = idx >> 6, k = idx & 63;
            float kv = g_K[base + (size_t)d * SEQ + t0 + k];
            uint32_t kh = f2tf(kv);
            int slot = d * KSTR + (k & 7) * 12 + (k >> 3);
            Khi[slot] = __uint_as_float(kh);
            Klo[slot] = __uint_as_float(f2tf(kv - __uint_as_float(kh)));
            Vs[d * 68 + k] = __uint_as_float(f2tf(g_V[base + (size_t)d * SEQ + t0 + k]));
        }
        __syncthreads();

        // ---- S = Q^T K (3x tf32), 3 passes over f per ks ----
        float S[8][4];
#pragma unroll
        for (int f = 0; f < 8; f++)
#pragma unroll
            for (int j = 0; j < 4; j++) S[f][j] = 0.f;

#pragma unroll
        for (int ks = 0; ks < 12; ks++) {
            const int d0 = (8 * ks + c) * KSTR + r * 12;
            const int d1 = (8 * ks + c + 4) * KSTR + r * 12;
            float4 H0a = *(const float4*)&Khi[d0];
            float4 H0b = *(const float4*)&Khi[d0 + 4];
            float4 H1a = *(const float4*)&Khi[d1];
            float4 H1b = *(const float4*)&Khi[d1 + 4];
            float4 L0a = *(const float4*)&Klo[d0];
            float4 L0b = *(const float4*)&Klo[d0 + 4];
            float4 L1a = *(const float4*)&Klo[d1];
            float4 L1b = *(const float4*)&Klo[d1 + 4];
            float4 ql = *(const float4*)&QLO[ks * 128 + lane * 4];
            uint32_t qlo0 = __float_as_uint(ql.x), qlo1 = __float_as_uint(ql.y);
            uint32_t qlo2 = __float_as_uint(ql.z), qlo3 = __float_as_uint(ql.w);
            uint32_t bh0[8] = {__float_as_uint(H0a.x), __float_as_uint(H0a.y),
                               __float_as_uint(H0a.z), __float_as_uint(H0a.w),
                               __float_as_uint(H0b.x), __float_as_uint(H0b.y),
                               __float_as_uint(H0b.z), __float_as_uint(H0b.w)};
            uint32_t bh1[8] = {__float_as_uint(H1a.x), __float_as_uint(H1a.y),
                               __float_as_uint(H1a.z), __float_as_uint(H1a.w),
                               __float_as_uint(H1b.x), __float_as_uint(H1b.y),
                               __float_as_uint(H1b.z), __float_as_uint(H1b.w)};
            uint32_t bl0[8] = {__float_as_uint(L0a.x), __float_as_uint(L0a.y),
                               __float_as_uint(L0a.z), __float_as_uint(L0a.w),
                               __float_as_uint(L0b.x), __float_as_uint(L0b.y),
                               __float_as_uint(L0b.z), __float_as_uint(L0b.w)};
            uint32_t bl1[8] = {__float_as_uint(L1a.x), __float_as_uint(L1a.y),
                               __float_as_uint(L1a.z), __float_as_uint(L1a.w),
                               __float_as_uint(L1b.x), __float_as_uint(L1b.y),
                               __float_as_uint(L1b.z), __float_as_uint(L1b.w)};
            // pass 1: hi * K-hi  (8 independent accumulator chains)
#pragma unroll
            for (int f = 0; f < 8; f++)
                mma_tf32(S[f][0], S[f][1], S[f][2], S[f][3],
                         qhi[ks][0], qhi[ks][1], qhi[ks][2], qhi[ks][3],
                         bh0[f], bh1[f]);
            // pass 2: hi * K-lo
#pragma unroll
            for (int f = 0; f < 8; f++)
                mma_tf32(S[f][0], S[f][1], S[f][2], S[f][3],
                         qhi[ks][0], qhi[ks][1], qhi[ks][2], qhi[ks][3],
                         bl0[f], bl1[f]);
            // pass 3: lo * K-hi
#pragma unroll
            for (int f = 0; f < 8; f++)
                mma_tf32(S[f][0], S[f][1], S[f][2], S[f][3],
                         qlo0, qlo1, qlo2, qlo3,
                         bh0[f], bh1[f]);
        }

        // ---- online softmax ----
#pragma unroll
        for (int half = 0; half < 2; half++) {
            float mx = -1e30f;
#pragma unroll
            for (int f = 0; f < 8; f++)
                mx = fmaxf(mx, fmaxf(S[f][2 * half], S[f][2 * half + 1]));
            mx = fmaxf(mx, __shfl_xor_sync(0xFFFFFFFFu, mx, 1));
            mx = fmaxf(mx, __shfl_xor_sync(0xFFFFFFFFu, mx, 2));
            float mnew = fmaxf(mrow[half], mx);
            float al = __expf(mrow[half] - mnew);
            float rs = 0.f;
#pragma unroll
            for (int f = 0; f < 8; f++) {
                float p0 = __expf(S[f][2 * half] - mnew);
                float p1 = __expf(S[f][2 * half + 1] - mnew);
                rs += p0 + p1;
                *(float2*)&Pshi[(r + 8 * half) * 68 + f * 8 + 2 * c] =
                    make_float2(__uint_as_float(f2tf(p0)), __uint_as_float(f2tf(p1)));
            }
            rs += __shfl_xor_sync(0xFFFFFFFFu, rs, 1);
            rs += __shfl_xor_sync(0xFFFFFFFFu, rs, 2);
            lrow[half] = lrow[half] * al + rs;
            mrow[half] = mnew;
#pragma unroll
            for (int f = 0; f < 12; f++) {
                O[f][2 * half]     *= al;
                O[f][2 * half + 1] *= al;
            }
        }
        __syncwarp();

        // ---- O += P @ V^T (single tf32) ----
#pragma unroll
        for (int ks = 0; ks < 8; ks++) {
            uint32_t a0 = __float_as_uint(Pshi[r * 68 + ks * 8 + c]);
            uint32_t a1 = __float_as_uint(Pshi[(r + 8) * 68 + ks * 8 + c]);
            uint32_t a2 = __float_as_uint(Pshi[r * 68 + ks * 8 + c + 4]);
            uint32_t a3 = __float_as_uint(Pshi[(r + 8) * 68 + ks * 8 + c + 4]);
#pragma unroll
            for (int f = 0; f < 12; f++) {
                uint32_t b0 = __float_as_uint(Vs[(f * 8 + r) * 68 + ks * 8 + c]);
                uint32_t b1 = __float_as_uint(Vs[(f * 8 + r) * 68 + ks * 8 + c + 4]);
                mma_tf32(O[f][0], O[f][1], O[f][2], O[f][3], a0, a1, a2, a3, b0, b1);
            }
        }
        __syncwarp();
    }

    float inv0 = 1.f / lrow[0];
    float inv1 = 1.f / lrow[1];
#pragma unroll
    for (int f = 0; f < 12; f++) {
        int d0 = f * 8 + 2 * c;
        int qa = q0 + w * 16 + r;
        out[base + (size_t)d0 * SEQ + qa]           = O[f][0] * inv0;
        out[base + (size_t)(d0 + 1) * SEQ + qa]     = O[f][1] * inv0;
        out[base + (size_t)d0 * SEQ + qa + 8]       = O[f][2] * inv1;
        out[base + (size_t)(d0 + 1) * SEQ + qa + 8] = O[f][3] * inv1;
    }
}

// ---------------------------------------------------------------------------
extern "C" void kernel_launch(void* const* d_in, const int* in_sizes, int n_in,
                              void* d_out, int out_size)
{
    (void)in_sizes; (void)n_in; (void)out_size;
    const float* x1 = (const float*)d_in[0];
    const float* x2 = (const float*)d_in[1];
    const float* Wq = (const float*)d_in[2];
    const float* bq = (const float*)d_in[3];
    const float* Wk = (const float*)d_in[4];
    const float* bk = (const float*)d_in[5];
    const float* Wv = (const float*)d_in[6];
    const float* bv = (const float*)d_in[7];
    float* out = (float*)d_out;

    cudaFuncSetAttribute(proj_mma<true>, cudaFuncAttributeMaxDynamicSharedMemorySize,
                         PROJ_SMEM_SPLIT);
    cudaFuncSetAttribute(proj_mma<false>, cudaFuncAttributeMaxDynamicSharedMemorySize,
                         PROJ_SMEM_ONE);
    cudaFuncSetAttribute(attn_mma, cudaFuncAttributeMaxDynamicSharedMemorySize,
                         ATTN_SMEM_BYTES);

    proj_mma<true><<<dim3(9, 64, 2), 256, PROJ_SMEM_SPLIT>>>(
        x1, x2, Wq, bq, Wk, bk, Wv, bv);
    proj_mma<false><<<dim3(9, 64, 1), 256, PROJ_SMEM_ONE>>>(
        x1, x2, Wq, bq, Wk, bk, Wv, bv);
    attn_mma<<<dim3(8, NHEAD, NB), 256, ATTN_SMEM_BYTES>>>(out);
}

// round 7
// speedup vs baseline: 2.3209x; 1.1212x over previous
#include <cuda_runtime.h>
#include <cstdint>

#define NB    8
#define SEQ   1024
#define CH    576
#define NHEAD 6
#define HDIM  96

// raw projection outputs (scrambled view [b][h][d][t])
__device__ float g_Q[NB*SEQ*CH];
__device__ float g_K[NB*SEQ*CH];
__device__ float g_V[NB*SEQ*CH];

// pre-decomposed, tile-layout K and V for the attention kernel.
// K tile: [96 rows][104], slot(d, k) = d*104 + (k&7)*12 + (k>>3)   (k = t&63)
// V tile: [64 rows][104], slot(k, d) = k*104 + (d&7)*12 + (d>>3)
#define KT_FLOATS 9984      // 96*104
#define VT_FLOATS 6656      // 64*104
#define NTILE     16
__device__ float g_KhiP[NB*NHEAD*NTILE*KT_FLOATS];
__device__ float g_KloP[NB*NHEAD*NTILE*KT_FLOATS];
__device__ float g_VP  [NB*NHEAD*NTILE*VT_FLOATS];

__device__ __forceinline__ uint32_t f2tf(float x) {
    uint32_t u;
    asm("cvt.rna.tf32.f32 %0, %1;" : "=r"(u) : "f"(x));
    return u;
}

__device__ __forceinline__ void mma_tf32(float& d0, float& d1, float& d2, float& d3,
                                         uint32_t a0, uint32_t a1, uint32_t a2, uint32_t a3,
                                         uint32_t b0, uint32_t b1) {
    asm volatile(
        "mma.sync.aligned.m16n8k8.row.col.f32.tf32.tf32.f32 "
        "{%0,%1,%2,%3},{%4,%5,%6,%7},{%8,%9},{%0,%1,%2,%3};"
        : "+f"(d0), "+f"(d1), "+f"(d2), "+f"(d3)
        : "r"(a0), "r"(a1), "r"(a2), "r"(a3), "r"(b0), "r"(b1));
}

__device__ __forceinline__ void cp16(uint32_t dst_smem, const void* src) {
    asm volatile("cp.async.cg.shared.global [%0], [%1], 16;\n"
                 :: "r"(dst_smem), "l"(src));
}
#define CP_COMMIT() asm volatile("cp.async.commit_group;\n" ::: "memory")
#define CP_WAIT(n)  asm volatile("cp.async.wait_group %0;\n" :: "n"(n) : "memory")

// ---------------------------------------------------------------------------
// Projection: Y = X @ W^T + bias.  SPLIT: 3x-tf32 (Q,K); !SPLIT: 1x tf32 (V).
// (unchanged from R6)
// ---------------------------------------------------------------------------
#define PROJ_SMEM_SPLIT ((2*128*36 + 2*64*36) * 4)
#define PROJ_SMEM_ONE   ((128*36 + 64*36) * 4)

template<bool SPLIT>
__global__ __launch_bounds__(256) void proj_mma(
    const float* __restrict__ x1, const float* __restrict__ x2,
    const float* __restrict__ Wq, const float* __restrict__ bq,
    const float* __restrict__ Wk, const float* __restrict__ bk,
    const float* __restrict__ Wv, const float* __restrict__ bv)
{
    const int which = SPLIT ? blockIdx.z : 2;
    const float* X    = (which == 0) ? x1 : x2;
    const float* W    = (which == 0) ? Wq : (which == 1) ? Wk : Wv;
    const float* bias = (which == 0) ? bq : (which == 1) ? bk : bv;
    float*       Y    = (which == 0) ? g_Q : (which == 1) ? g_K : g_V;

    extern __shared__ float sp[];
    float* Xhi = sp;
    float* Whi = sp + 128*36;
    float* Xlo = sp + 128*36 + 64*36;
    float* Wlo = sp + 2*128*36 + 64*36;

    const int tid  = threadIdx.x;
    const int lane = tid & 31;
    const int w    = tid >> 5;
    const int wm   = w & 3, wn = w >> 2;
    const int r    = lane >> 2, c = lane & 3;
    const int n0   = blockIdx.x * 64;
    const int m0   = blockIdx.y * 128;

    float acc[2][4][4];
#pragma unroll
    for (int mi = 0; mi < 2; mi++)
#pragma unroll
        for (int f = 0; f < 4; f++)
#pragma unroll
            for (int j = 0; j < 4; j++) acc[mi][f][j] = 0.f;

    const int lrow = tid >> 3;
    const int lcol = (tid & 7) * 4;

    for (int c0 = 0; c0 < CH; c0 += 32) {
        __syncthreads();
#pragma unroll
        for (int p = 0; p < 4; p++) {
            int m = lrow + p * 32;
            float4 xv = *(const float4*)&X[(size_t)(m0 + m) * CH + c0 + lcol];
            float xs[4] = {xv.x, xv.y, xv.z, xv.w};
#pragma unroll
            for (int j = 0; j < 4; j++) {
                uint32_t hb = f2tf(xs[j]);
                Xhi[m * 36 + lcol + j] = __uint_as_float(hb);
                if (SPLIT)
                    Xlo[m * 36 + lcol + j] =
                        __uint_as_float(f2tf(xs[j] - __uint_as_float(hb)));
            }
        }
#pragma unroll
        for (int p = 0; p < 2; p++) {
            int n = lrow + p * 32;
            float4 wv = *(const float4*)&W[(size_t)(n0 + n) * CH + c0 + lcol];
            float ws[4] = {wv.x, wv.y, wv.z, wv.w};
#pragma unroll
            for (int j = 0; j < 4; j++) {
                uint32_t hb = f2tf(ws[j]);
                Whi[n * 36 + lcol + j] = __uint_as_float(hb);
                if (SPLIT)
                    Wlo[n * 36 + lcol + j] =
                        __uint_as_float(f2tf(ws[j] - __uint_as_float(hb)));
            }
        }
        __syncthreads();

#pragma unroll
        for (int ks = 0; ks < 4; ks++) {
            const int k = ks * 8 + c;
            uint32_t ahi[2][4], alo[2][4], bhi[4][2], blo[4][2];
#pragma unroll
            for (int mi = 0; mi < 2; mi++) {
                int mm = wm * 32 + mi * 16;
                ahi[mi][0] = __float_as_uint(Xhi[(mm + r) * 36 + k]);
                ahi[mi][1] = __float_as_uint(Xhi[(mm + r + 8) * 36 + k]);
                ahi[mi][2] = __float_as_uint(Xhi[(mm + r) * 36 + k + 4]);
                ahi[mi][3] = __float_as_uint(Xhi[(mm + r + 8) * 36 + k + 4]);
                if (SPLIT) {
                    alo[mi][0] = __float_as_uint(Xlo[(mm + r) * 36 + k]);
                    alo[mi][1] = __float_as_uint(Xlo[(mm + r + 8) * 36 + k]);
                    alo[mi][2] = __float_as_uint(Xlo[(mm + r) * 36 + k + 4]);
                    alo[mi][3] = __float_as_uint(Xlo[(mm + r + 8) * 36 + k + 4]);
                }
            }
#pragma unroll
            for (int f = 0; f < 4; f++) {
                int nn = wn * 32 + f * 8 + r;
                bhi[f][0] = __float_as_uint(Whi[nn * 36 + k]);
                bhi[f][1] = __float_as_uint(Whi[nn * 36 + k + 4]);
                if (SPLIT) {
                    blo[f][0] = __float_as_uint(Wlo[nn * 36 + k]);
                    blo[f][1] = __float_as_uint(Wlo[nn * 36 + k + 4]);
                }
            }
#pragma unroll
            for (int mi = 0; mi < 2; mi++)
#pragma unroll
                for (int f = 0; f < 4; f++) {
                    mma_tf32(acc[mi][f][0], acc[mi][f][1], acc[mi][f][2], acc[mi][f][3],
                             ahi[mi][0], ahi[mi][1], ahi[mi][2], ahi[mi][3],
                             bhi[f][0], bhi[f][1]);
                    if (SPLIT) {
                        mma_tf32(acc[mi][f][0], acc[mi][f][1], acc[mi][f][2], acc[mi][f][3],
                                 ahi[mi][0], ahi[mi][1], ahi[mi][2], ahi[mi][3],
                                 blo[f][0], blo[f][1]);
                        mma_tf32(acc[mi][f][0], acc[mi][f][1], acc[mi][f][2], acc[mi][f][3],
                                 alo[mi][0], alo[mi][1], alo[mi][2], alo[mi][3],
                                 bhi[f][0], bhi[f][1]);
                    }
                }
        }
    }

#pragma unroll
    for (int mi = 0; mi < 2; mi++)
#pragma unroll
        for (int f = 0; f < 4; f++) {
            int n = n0 + wn * 32 + f * 8 + 2 * c;
            float b0 = bias[n], b1 = bias[n + 1];
            int m = m0 + wm * 32 + mi * 16 + r;
            float2 o0 = make_float2(acc[mi][f][0] + b0, acc[mi][f][1] + b1);
            float2 o1 = make_float2(acc[mi][f][2] + b0, acc[mi][f][3] + b1);
            *(float2*)&Y[(size_t)m * CH + n] = o0;
            *(float2*)&Y[(size_t)(m + 8) * CH + n] = o1;
        }
}

// ---------------------------------------------------------------------------
// Repack: K -> (hi,lo) tf32 tiles, V -> tf32 tiles, in attn smem layout.
// grid (16 tiles, 6 heads, 8 batch), 256 threads, smem staging.
// ---------------------------------------------------------------------------
#define RK_SMEM_BYTES ((2*KT_FLOATS + VT_FLOATS) * 4)

__global__ __launch_bounds__(256) void repack_kv()
{
    extern __shared__ float s[];
    float* sKhi = s;
    float* sKlo = s + KT_FLOATS;
    float* sV   = s + 2*KT_FLOATS;

    const int tile = blockIdx.x, h = blockIdx.y, b = blockIdx.z;
    const size_t base = (size_t)b*(SEQ*CH) + (size_t)h*(HDIM*SEQ) + (size_t)tile*64;

    for (int idx = threadIdx.x; idx < HDIM*64; idx += 256) {
        int d = idx >> 6, k = idx & 63;
        float kv = g_K[base + (size_t)d*SEQ + k];
        uint32_t hi = f2tf(kv);
        int slot = d*104 + (k&7)*12 + (k>>3);
        sKhi[slot] = __uint_as_float(hi);
        sKlo[slot] = __uint_as_float(f2tf(kv - __uint_as_float(hi)));
        float vv = g_V[base + (size_t)d*SEQ + k];
        sV[k*104 + (d&7)*12 + (d>>3)] = __uint_as_float(f2tf(vv));
    }
    __syncthreads();

    size_t tb = (size_t)((b*NHEAD + h)*NTILE + tile);
    float* gkh = g_KhiP + tb * KT_FLOATS;
    float* gkl = g_KloP + tb * KT_FLOATS;
    float* gv  = g_VP   + tb * VT_FLOATS;
    for (int i = threadIdx.x; i < KT_FLOATS; i += 256) {
        gkh[i] = sKhi[i];
        gkl[i] = sKlo[i];
    }
    for (int i = threadIdx.x; i < VT_FLOATS; i += 256)
        gv[i] = sV[i];
}

// ---------------------------------------------------------------------------
// Fused attention, cp.async pipelined. 256 thr = 8 warps, q-tile 128, TK=64.
// smem (floats):
//   KB   @0      : Khi double buffer 2*9984 = 19968   (union: Qst 96*136 init)
//   Klo  @19968  : 9984
//   Vs   @29952  : 6656
//   QLO  @36608  : 8*12*128 = 12288
//   Pshi @48896  : 8*16*68  = 8704
//   total 57600 floats = 230400 B
// ---------------------------------------------------------------------------
#define SM_KB  0
#define SM_KLO 19968
#define SM_VS  29952
#define SM_QLO 36608
#define SM_PS  48896
#define ATTN_SMEM_FLOATS 57600
#define ATTN_SMEM_BYTES  (ATTN_SMEM_FLOATS*4)

__global__ __launch_bounds__(256, 1) void attn_mma(float* __restrict__ out)
{
    extern __shared__ float sm[];
    float* KB   = sm + SM_KB;
    float* Klo  = sm + SM_KLO;
    float* Vs   = sm + SM_VS;
    float* QLO  = sm + SM_QLO + (threadIdx.x >> 5) * (12 * 128);
    float* Pshi = sm + SM_PS  + (threadIdx.x >> 5) * (16 * 68);
    float* Qst  = sm + SM_KB;   // staging, overwritten by K tiles later

    const int tid  = threadIdx.x;
    const int lane = tid & 31;
    const int w    = tid >> 5;
    const int r    = lane >> 2;
    const int c    = lane & 3;
    const int q0   = blockIdx.x * 128;
    const int bh   = blockIdx.z * NHEAD + blockIdx.y;
    const size_t base = (size_t)blockIdx.z * (SEQ * CH) + (size_t)blockIdx.y * (HDIM * SEQ);

    const char* gkh = (const char*)(g_KhiP + (size_t)bh * NTILE * KT_FLOATS);
    const char* gkl = (const char*)(g_KloP + (size_t)bh * NTILE * KT_FLOATS);
    const char* gv  = (const char*)(g_VP   + (size_t)bh * NTILE * VT_FLOATS);
    const uint32_t sKB  = (uint32_t)__cvta_generic_to_shared(sm + SM_KB);
    const uint32_t sKLO = (uint32_t)__cvta_generic_to_shared(sm + SM_KLO);
    const uint32_t sVS  = (uint32_t)__cvta_generic_to_shared(sm + SM_VS);

    // ---- stage Q, build fragments ----
    for (int idx = tid; idx < HDIM * 128; idx += 256) {
        int d = idx >> 7, q = idx & 127;
        Qst[d * 136 + q] = g_Q[base + (size_t)d * SEQ + q0 + q];
    }
    __syncthreads();

    uint32_t qhi[12][4];
    const int qm = w * 16 + r;
#pragma unroll
    for (int ks = 0; ks < 12; ks++) {
        float v0 = Qst[(8 * ks + c) * 136 + qm];
        float v1 = Qst[(8 * ks + c) * 136 + qm + 8];
        float v2 = Qst[(8 * ks + c + 4) * 136 + qm];
        float v3 = Qst[(8 * ks + c + 4) * 136 + qm + 8];
        qhi[ks][0] = f2tf(v0);
        qhi[ks][1] = f2tf(v1);
        qhi[ks][2] = f2tf(v2);
        qhi[ks][3] = f2tf(v3);
        float4 lo;
        lo.x = __uint_as_float(f2tf(v0 - __uint_as_float(qhi[ks][0])));
        lo.y = __uint_as_float(f2tf(v1 - __uint_as_float(qhi[ks][1])));
        lo.z = __uint_as_float(f2tf(v2 - __uint_as_float(qhi[ks][2])));
        lo.w = __uint_as_float(f2tf(v3 - __uint_as_float(qhi[ks][3])));
        *(float4*)&QLO[ks * 128 + lane * 4] = lo;
    }
    __syncthreads();   // Qst reads done; K tiles may overwrite

    // ---- preload K tile 0 (hi -> buf0, lo) ----
    {
        const int nch = KT_FLOATS / 4;   // 2496 chunks
        for (int i = tid; i < nch; i += 256) {
            cp16(sKB  + i * 16, gkh + i * 16);
            cp16(sKLO + i * 16, gkl + i * 16);
        }
        CP_COMMIT();
    }

    float O[12][4];
#pragma unroll
    for (int f = 0; f < 12; f++)
#pragma unroll
        for (int j = 0; j < 4; j++) O[f][j] = 0.f;
    float mrow[2] = {-1e30f, -1e30f};
    float lrow[2] = {0.f, 0.f};

    for (int t = 0; t < NTILE; t++) {
        __syncthreads();   // prev PV done: Vs writable, K[t+1... ] buffers settled

        // issue V[t]
        {
            const char* src = gv + (size_t)t * VT_FLOATS * 4;
            const int nch = VT_FLOATS / 4;   // 1664
            for (int i = tid; i < nch; i += 256)
                cp16(sVS + i * 16, src + i * 16);
            CP_COMMIT();
        }

        CP_WAIT(1);        // K[t] group complete (committed before V[t])
        __syncthreads();   // K[t] visible CTA-wide

        const float* Khi = KB + (t & 1) * KT_FLOATS;

        // ---- S = Q^T K (3x tf32) ----
        float S[8][4];
#pragma unroll
        for (int f = 0; f < 8; f++)
#pragma unroll
            for (int j = 0; j < 4; j++) S[f][j] = 0.f;

#pragma unroll
        for (int ks = 0; ks < 12; ks++) {
            const int d0 = (8 * ks + c) * 104 + r * 12;
            const int d1 = (8 * ks + c + 4) * 104 + r * 12;
            float4 H0a = *(const float4*)&Khi[d0];
            float4 H0b = *(const float4*)&Khi[d0 + 4];
            float4 H1a = *(const float4*)&Khi[d1];
            float4 H1b = *(const float4*)&Khi[d1 + 4];
            float4 L0a = *(const float4*)&Klo[d0];
            float4 L0b = *(const float4*)&Klo[d0 + 4];
            float4 L1a = *(const float4*)&Klo[d1];
            float4 L1b = *(const float4*)&Klo[d1 + 4];
            float4 ql = *(const float4*)&QLO[ks * 128 + lane * 4];
            uint32_t qlo0 = __float_as_uint(ql.x), qlo1 = __float_as_uint(ql.y);
            uint32_t qlo2 = __float_as_uint(ql.z), qlo3 = __float_as_uint(ql.w);
            uint32_t bh0[8] = {__float_as_uint(H0a.x), __float_as_uint(H0a.y),
                               __float_as_uint(H0a.z), __float_as_uint(H0a.w),
                               __float_as_uint(H0b.x), __float_as_uint(H0b.y),
                               __float_as_uint(H0b.z), __float_as_uint(H0b.w)};
            uint32_t bh1[8] = {__float_as_uint(H1a.x), __float_as_uint(H1a.y),
                               __float_as_uint(H1a.z), __float_as_uint(H1a.w),
                               __float_as_uint(H1b.x), __float_as_uint(H1b.y),
                               __float_as_uint(H1b.z), __float_as_uint(H1b.w)};
            uint32_t bl0[8] = {__float_as_uint(L0a.x), __float_as_uint(L0a.y),
                               __float_as_uint(L0a.z), __float_as_uint(L0a.w),
                               __float_as_uint(L0b.x), __float_as_uint(L0b.y),
                               __float_as_uint(L0b.z), __float_as_uint(L0b.w)};
            uint32_t bl1[8] = {__float_as_uint(L1a.x), __float_as_uint(L1a.y),
                               __float_as_uint(L1a.z), __float_as_uint(L1a.w),
                               __float_as_uint(L1b.x), __float_as_uint(L1b.y),
                               __float_as_uint(L1b.z), __float_as_uint(L1b.w)};
#pragma unroll
            for (int f = 0; f < 8; f++)
                mma_tf32(S[f][0], S[f][1], S[f][2], S[f][3],
                         qhi[ks][0], qhi[ks][1], qhi[ks][2], qhi[ks][3],
                         bh0[f], bh1[f]);
#pragma unroll
            for (int f = 0; f < 8; f++)
                mma_tf32(S[f][0], S[f][1], S[f][2], S[f][3],
                         qhi[ks][0], qhi[ks][1], qhi[ks][2], qhi[ks][3],
                         bl0[f], bl1[f]);
#pragma unroll
            for (int f = 0; f < 8; f++)
                mma_tf32(S[f][0], S[f][1], S[f][2], S[f][3],
                         qlo0, qlo1, qlo2, qlo3,
                         bh0[f], bh1[f]);
        }

        // ---- online softmax ----
#pragma unroll
        for (int half = 0; half < 2; half++) {
            float mx = -1e30f;
#pragma unroll
            for (int f = 0; f < 8; f++)
                mx = fmaxf(mx, fmaxf(S[f][2 * half], S[f][2 * half + 1]));
            mx = fmaxf(mx, __shfl_xor_sync(0xFFFFFFFFu, mx, 1));
            mx = fmaxf(mx, __shfl_xor_sync(0xFFFFFFFFu, mx, 2));
            float mnew = fmaxf(mrow[half], mx);
            float al = __expf(mrow[half] - mnew);
            float rs = 0.f;
#pragma unroll
            for (int f = 0; f < 8; f++) {
                float p0 = __expf(S[f][2 * half] - mnew);
                float p1 = __expf(S[f][2 * half + 1] - mnew);
                rs += p0 + p1;
                *(float2*)&Pshi[(r + 8 * half) * 68 + f * 8 + 2 * c] =
                    make_float2(__uint_as_float(f2tf(p0)), __uint_as_float(f2tf(p1)));
            }
            rs += __shfl_xor_sync(0xFFFFFFFFu, rs, 1);
            rs += __shfl_xor_sync(0xFFFFFFFFu, rs, 2);
            lrow[half] = lrow[half] * al + rs;
            mrow[half] = mnew;
#pragma unroll
            for (int f = 0; f < 12; f++) {
                O[f][2 * half]     *= al;
                O[f][2 * half + 1] *= al;
            }
        }

        CP_WAIT(0);        // V[t] complete
        __syncthreads();   // Pshi + V visible; S reads of Klo/Khi done CTA-wide

        // issue K[t+1] (hi -> other buf, lo -> single buf)
        if (t < NTILE - 1) {
            const char* srch = gkh + (size_t)(t + 1) * KT_FLOATS * 4;
            const char* srcl = gkl + (size_t)(t + 1) * KT_FLOATS * 4;
            const uint32_t dsth = sKB + ((t + 1) & 1) * KT_FLOATS * 4;
            const int nch = KT_FLOATS / 4;
            for (int i = tid; i < nch; i += 256) {
                cp16(dsth + i * 16, srch + i * 16);
                cp16(sKLO + i * 16, srcl + i * 16);
            }
            CP_COMMIT();
        }

        // ---- O += P @ V^T (single tf32) ----
#pragma unroll
        for (int ks = 0; ks < 8; ks++) {
            uint32_t a0 = __float_as_uint(Pshi[r * 68 + ks * 8 + c]);
            uint32_t a1 = __float_as_uint(Pshi[(r + 8) * 68 + ks * 8 + c]);
            uint32_t a2 = __float_as_uint(Pshi[r * 68 + ks * 8 + c + 4]);
            uint32_t a3 = __float_as_uint(Pshi[(r + 8) * 68 + ks * 8 + c + 4]);
            const int vb0 = (8 * ks + c) * 104 + r * 12;
            const int vb1 = (8 * ks + c + 4) * 104 + r * 12;
            float4 V0a = *(const float4*)&Vs[vb0];
            float4 V0b = *(const float4*)&Vs[vb0 + 4];
            float4 V0c = *(const float4*)&Vs[vb0 + 8];
            float4 V1a = *(const float4*)&Vs[vb1];
            float4 V1b = *(const float4*)&Vs[vb1 + 4];
            float4 V1c = *(const float4*)&Vs[vb1 + 8];
            uint32_t b0[12] = {__float_as_uint(V0a.x), __float_as_uint(V0a.y),
                               __float_as_uint(V0a.z), __float_as_uint(V0a.w),
                               __float_as_uint(V0b.x), __float_as_uint(V0b.y),
                               __float_as_uint(V0b.z), __float_as_uint(V0b.w),
                               __float_as_uint(V0c.x), __float_as_uint(V0c.y),
                               __float_as_uint(V0c.z), __float_as_uint(V0c.w)};
            uint32_t b1[12] = {__float_as_uint(V1a.x), __float_as_uint(V1a.y),
                               __float_as_uint(V1a.z), __float_as_uint(V1a.w),
                               __float_as_uint(V1b.x), __float_as_uint(V1b.y),
                               __float_as_uint(V1b.z), __float_as_uint(V1b.w),
                               __float_as_uint(V1c.x), __float_as_uint(V1c.y),
                               __float_as_uint(V1c.z), __float_as_uint(V1c.w)};
#pragma unroll
            for (int f = 0; f < 12; f++)
                mma_tf32(O[f][0], O[f][1], O[f][2], O[f][3],
                         a0, a1, a2, a3, b0[f], b1[f]);
        }
    }

    float inv0 = 1.f / lrow[0];
    float inv1 = 1.f / lrow[1];
#pragma unroll
    for (int f = 0; f < 12; f++) {
        int d0 = f * 8 + 2 * c;
        int qa = q0 + w * 16 + r;
        out[base + (size_t)d0 * SEQ + qa]           = O[f][0] * inv0;
        out[base + (size_t)(d0 + 1) * SEQ + qa]     = O[f][1] * inv0;
        out[base + (size_t)d0 * SEQ + qa + 8]       = O[f][2] * inv1;
        out[base + (size_t)(d0 + 1) * SEQ + qa + 8] = O[f][3] * inv1;
    }
}

// ---------------------------------------------------------------------------
extern "C" void kernel_launch(void* const* d_in, const int* in_sizes, int n_in,
                              void* d_out, int out_size)
{
    (void)in_sizes; (void)n_in; (void)out_size;
    const float* x1 = (const float*)d_in[0];
    const float* x2 = (const float*)d_in[1];
    const float* Wq = (const float*)d_in[2];
    const float* bq = (const float*)d_in[3];
    const float* Wk = (const float*)d_in[4];
    const float* bk = (const float*)d_in[5];
    const float* Wv = (const float*)d_in[6];
    const float* bv = (const float*)d_in[7];
    float* out = (float*)d_out;

    cudaFuncSetAttribute(proj_mma<true>, cudaFuncAttributeMaxDynamicSharedMemorySize,
                         PROJ_SMEM_SPLIT);
    cudaFuncSetAttribute(proj_mma<false>, cudaFuncAttributeMaxDynamicSharedMemorySize,
                         PROJ_SMEM_ONE);
    cudaFuncSetAttribute(repack_kv, cudaFuncAttributeMaxDynamicSharedMemorySize,
                         RK_SMEM_BYTES);
    cudaFuncSetAttribute(attn_mma, cudaFuncAttributeMaxDynamicSharedMemorySize,
                         ATTN_SMEM_BYTES);

    proj_mma<true><<<dim3(9, 64, 2), 256, PROJ_SMEM_SPLIT>>>(
        x1, x2, Wq, bq, Wk, bk, Wv, bv);
    proj_mma<false><<<dim3(9, 64, 1), 256, PROJ_SMEM_ONE>>>(
        x1, x2, Wq, bq, Wk, bk, Wv, bv);
    repack_kv<<<dim3(NTILE, NHEAD, NB), 256, RK_SMEM_BYTES>>>();
    attn_mma<<<dim3(8, NHEAD, NB), 256, ATTN_SMEM_BYTES>>>(out);
}